// round 7
// baseline (speedup 1.0000x reference)
#include <cuda_runtime.h>
#include <cuda_fp16.h>
#include <cstdint>

#define B_   1024
#define G_   512
#define K_   128
#define J_   129
#define KJ_  16512
#define KE_  16640
#define NSPLIT_ 4
#define NCH_ 65
#define GSTAGES 3
#define STAGE_B 32768
#define SMEM_G (GSTAGES * STAGE_B)

// ---------------- device scratch ----------------
__device__ float d_wrecnorm[K_];
__device__ float d_wrec2norm[J_];
__device__ float d_wnorm1[K_];
__device__ float d_q[KJ_];
__device__ float d_corr[KJ_];
__device__ float d_qp[8][KJ_];
__device__ float d_cp[8][KJ_];
__device__ float d_wnp[8][K_];
__device__ float d_lg1p[4][B_][K_];
__device__ float d_xpd[B_ * K_];
__device__ int   d_idx[B_];
__device__ float d_xp2d[B_ * J_];
__device__ float d_dot2p[2][B_][J_];
__device__ __half d_Ph[(size_t)B_ * KE_];
__device__ __half d_w2h[(size_t)G_ * KE_];
__device__ float d_c2[NSPLIT_][B_][G_];
// idx grouping
__device__ int d_cnt[K_];
__device__ int d_off[K_];
__device__ int d_pos[K_];
__device__ int d_blist[B_];

// ---------------- helpers ----------------
__device__ __forceinline__ uint32_t s2u(const void* p) {
    uint32_t r;
    asm("{ .reg .u64 t; cvta.to.shared.u64 t, %1; cvt.u32.u64 %0, t; }" : "=r"(r) : "l"(p));
    return r;
}
__device__ __forceinline__ void cp16(uint32_t dst, const void* src) {
    asm volatile("cp.async.cg.shared.global [%0], [%1], 16;" :: "r"(dst), "l"(src) : "memory");
}
#define SWZ(o) ((o) ^ ((((unsigned)(o)) >> 3) & 0x70u))

__device__ __forceinline__ void mma_f16(float* c, const uint32_t* a, const uint32_t* b) {
    asm volatile(
        "mma.sync.aligned.m16n8k16.row.col.f32.f16.f16.f32 "
        "{%0,%1,%2,%3}, {%4,%5,%6,%7}, {%8,%9}, {%0,%1,%2,%3};"
        : "+f"(c[0]), "+f"(c[1]), "+f"(c[2]), "+f"(c[3])
        : "r"(a[0]), "r"(a[1]), "r"(a[2]), "r"(a[3]), "r"(b[0]), "r"(b[1]));
}
__device__ __forceinline__ void mma_tf32(float* c, const uint32_t* a, const uint32_t* b) {
    asm volatile(
        "mma.sync.aligned.m16n8k8.row.col.f32.tf32.tf32.f32 "
        "{%0,%1,%2,%3}, {%4,%5,%6,%7}, {%8,%9}, {%0,%1,%2,%3};"
        : "+f"(c[0]), "+f"(c[1]), "+f"(c[2]), "+f"(c[3])
        : "r"(a[0]), "r"(a[1]), "r"(a[2]), "r"(a[3]), "r"(b[0]), "r"(b[1]));
}
__device__ __forceinline__ unsigned div129(unsigned kj) { return (kj * 32515u) >> 22; }
__device__ __forceinline__ float wmax(float v) {
#pragma unroll
    for (int o = 16; o; o >>= 1) v = fmaxf(v, __shfl_xor_sync(~0u, v, o));
    return v;
}
__device__ __forceinline__ float wsum(float v) {
#pragma unroll
    for (int o = 16; o; o >>= 1) v += __shfl_xor_sync(~0u, v, o);
    return v;
}

// ---------------- wimg2 pass ----------------
__global__ void k_prep1(const float* __restrict__ wimg,
                        const float* __restrict__ wimg2) {
    int t = blockIdx.x * 256 + threadIdx.x;
    int gh = blockIdx.y;
    int gbeg = gh * 64;
    if (t < KJ_) {
        unsigned k = div129((unsigned)t);
        float q = 0.f, c = 0.f;
        for (int gg = 0; gg < 64; ++gg) {
            int g = gbeg + gg;
            float v = wimg2[(size_t)g * KJ_ + t];
            float wi = wimg[g * K_ + k];
            q += v * v;
            c += wi * v;
            d_w2h[(size_t)g * KE_ + t] = __float2half(v);
        }
        d_qp[gh][t] = q;
        d_cp[gh][t] = c;
    } else if (t < KE_) {
        int kk = t - KJ_;
        float s = 0.f;
        for (int gg = 0; gg < 64; ++gg) {
            int g = gbeg + gg;
            float v = wimg[g * K_ + kk];
            s += v * v;
            d_w2h[(size_t)g * KE_ + t] = __float2half(v);
        }
        d_wnp[gh][kk] = s;
    }
}

__global__ void k_qred() {
    int t = blockIdx.x * 256 + threadIdx.x;
    if (t < KJ_) {
        float q = 0.f, c = 0.f;
#pragma unroll
        for (int h = 0; h < 8; ++h) { q += d_qp[h][t]; c += d_cp[h][t]; }
        d_q[t] = q;
        d_corr[t] = c;
    } else if (t < KE_) {
        int kk = t - KJ_;
        float s = 0.f;
#pragma unroll
        for (int h = 0; h < 8; ++h) s += d_wnp[h][kk];
        d_wnorm1[kk] = s;
    }
}

__global__ void k_norms(const float* __restrict__ wrec,
                        const float* __restrict__ wrec2) {
    int t = threadIdx.x;
    if (t < K_) {
        float s = 0.f; const float* r = wrec + t * 128;
        for (int e = 0; e < 128; ++e) s += r[e] * r[e];
        d_wrecnorm[t] = s;
    }
    if (t < J_) {
        float s = 0.f; const float* r = wrec2 + t * 128;
        for (int e = 0; e < 128; ++e) s += r[e] * r[e];
        d_wrec2norm[t] = s;
    }
}

// ---------------- logits1 via tf32 mma: grid (8 b-tiles, 4 k-splits) ----------------
// C[b,k] partial = sum_{g in split} images[b,g] * wimg[g,k]
__global__ __launch_bounds__(256) void k_log1t(const float* __restrict__ images,
                                               const float* __restrict__ wimg) {
    __shared__ float As[128 * 36];   // images tile [128b x 32g], stride 36
    __shared__ float Bs[32 * 132];   // wimg tile  [32g x 128k], stride 132

    int tid = threadIdx.x, lane = tid & 31, wid = tid >> 5;
    int wm = wid >> 2, wn = wid & 3;
    int row_l = lane >> 2, kq = lane & 3;
    int b0 = blockIdx.x * 128, ks = blockIdx.y;
    uint32_t asb = s2u(As), bsb = s2u(Bs);

    float acc[4][4][4];
#pragma unroll
    for (int mt = 0; mt < 4; ++mt)
#pragma unroll
        for (int nt = 0; nt < 4; ++nt)
#pragma unroll
            for (int q = 0; q < 4; ++q) acc[mt][nt][q] = 0.f;

    for (int c = 0; c < 4; ++c) {
        int g0 = ks * 128 + c * 32;
        // A: 128 rows x 8 chunks of 16B
#pragma unroll
        for (int p = 0; p < 4; ++p) {
            int i = tid + p * 256;
            int row = i >> 3, c4 = (i & 7) << 2;
            cp16(asb + (row * 36 + c4) * 4, images + (size_t)(b0 + row) * 512 + g0 + c4);
        }
        // B: 32 rows x 32 chunks of 16B
#pragma unroll
        for (int p = 0; p < 4; ++p) {
            int i = tid + p * 256;
            int row = i >> 5, c4 = (i & 31) << 2;
            cp16(bsb + (row * 132 + c4) * 4, wimg + (size_t)(g0 + row) * 128 + c4);
        }
        asm volatile("cp.async.commit_group;" ::: "memory");
        asm volatile("cp.async.wait_group 0;" ::: "memory");
        __syncthreads();

#pragma unroll
        for (int kst = 0; kst < 4; ++kst) {
            uint32_t af[4][4];
#pragma unroll
            for (int mt = 0; mt < 4; ++mt) {
                int m = wm * 64 + mt * 16 + row_l;
                const float* ap = As + m * 36 + kst * 8 + kq;
                af[mt][0] = __float_as_uint(ap[0]);
                af[mt][1] = __float_as_uint(ap[8 * 36]);
                af[mt][2] = __float_as_uint(ap[4]);
                af[mt][3] = __float_as_uint(ap[8 * 36 + 4]);
            }
            uint32_t bf[4][2];
#pragma unroll
            for (int nt = 0; nt < 4; ++nt) {
                int n = wn * 32 + nt * 8 + row_l;
                const float* bp = Bs + (kst * 8 + kq) * 132 + n;
                bf[nt][0] = __float_as_uint(bp[0]);
                bf[nt][1] = __float_as_uint(bp[4 * 132]);
            }
#pragma unroll
            for (int mt = 0; mt < 4; ++mt)
#pragma unroll
                for (int nt = 0; nt < 4; ++nt)
                    mma_tf32(acc[mt][nt], af[mt], bf[nt]);
        }
        __syncthreads();
    }

#pragma unroll
    for (int mt = 0; mt < 4; ++mt)
#pragma unroll
        for (int nt = 0; nt < 4; ++nt) {
            int row = b0 + wm * 64 + mt * 16 + row_l;
            int col = wn * 32 + nt * 8 + kq * 2;
            *(float2*)&d_lg1p[ks][row][col]     = make_float2(acc[mt][nt][0], acc[mt][nt][1]);
            *(float2*)&d_lg1p[ks][row + 8][col] = make_float2(acc[mt][nt][2], acc[mt][nt][3]);
        }
}

// ---------------- softmax1 -> lat -> logits2 -> softmax2+argmax ----------------
#define SMEM_L2 ((16512 + 1024 + 1024 + 1024) * 4)
__global__ void k_latlog2(const float* __restrict__ wrec) {
    extern __shared__ float sm[];
    float* wrec_s = sm;
    float* xp1_s  = wrec_s + 16512;
    float* lat_s  = xp1_s + 1024;
    float* lg2_s  = lat_s + 1024;

    int t = threadIdx.x, lane = t & 31, w = t >> 5;
    int b0 = blockIdx.x * 8;
    int b = b0 + w;

    for (int i = t; i < 16384; i += 256)
        wrec_s[(i >> 7) * 129 + (i & 127)] = wrec[i];

    {
        float v[4];
#pragma unroll
        for (int q = 0; q < 4; ++q) {
            int k = q * 32 + lane;
            float d = d_lg1p[0][b][k] + d_lg1p[1][b][k] + d_lg1p[2][b][k] + d_lg1p[3][b][k];
            v[q] = (2.f * d - d_wnorm1[k]) * (1.f / 512.f);
        }
        float m = fmaxf(fmaxf(v[0], v[1]), fmaxf(v[2], v[3]));
        m = wmax(m);
        float e0 = __expf(v[0] - m), e1 = __expf(v[1] - m);
        float e2 = __expf(v[2] - m), e3 = __expf(v[3] - m);
        float s = wsum(e0 + e1 + e2 + e3);
        float inv = 1.f / s;
        xp1_s[w * 128 + lane]      = e0 * inv;
        xp1_s[w * 128 + 32 + lane] = e1 * inv;
        xp1_s[w * 128 + 64 + lane] = e2 * inv;
        xp1_s[w * 128 + 96 + lane] = e3 * inv;
    }
    __syncthreads();

    for (int i = t; i < 1024; i += 256) {
        int bi = i >> 7, e = i & 127;
        float acc = 0.f;
        const float* xp = xp1_s + bi * 128;
#pragma unroll 4
        for (int k = 0; k < 128; ++k) acc += xp[k] * wrec_s[k * 129 + e];
        lat_s[i] = acc;
    }
    __syncthreads();

    for (int i = t; i < 1024; i += 256) {
        int bi = i >> 7, tt = i & 127;
        float acc = 0.f;
        const float* lt = lat_s + bi * 128;
#pragma unroll 4
        for (int e = 0; e < 128; ++e) acc += lt[e] * wrec_s[tt * 129 + e];
        lg2_s[i] = (2.f * acc - d_wrecnorm[tt]) * (1.f / 128.f);
    }
    __syncthreads();

    {
        float v[4];
#pragma unroll
        for (int q = 0; q < 4; ++q) v[q] = lg2_s[w * 128 + q * 32 + lane];
        float bv = v[0]; int bk = lane;
#pragma unroll
        for (int q = 1; q < 4; ++q)
            if (v[q] > bv) { bv = v[q]; bk = q * 32 + lane; }
#pragma unroll
        for (int o = 16; o; o >>= 1) {
            float ov = __shfl_xor_sync(~0u, bv, o);
            int   ok = __shfl_xor_sync(~0u, bk, o);
            if (ov > bv || (ov == bv && ok < bk)) { bv = ov; bk = ok; }
        }
        if (lane == 0) d_idx[b] = bk;
        float m = bv;
        float e0 = __expf(v[0] - m), e1 = __expf(v[1] - m);
        float e2 = __expf(v[2] - m), e3 = __expf(v[3] - m);
        float s = wsum(e0 + e1 + e2 + e3);
        float inv = 1.f / s;
        d_xpd[b * 128 + lane]      = e0 * inv;
        d_xpd[b * 128 + 32 + lane] = e1 * inv;
        d_xpd[b * 128 + 64 + lane] = e2 * inv;
        d_xpd[b * 128 + 96 + lane] = e3 * inv;
    }
}

// ---------------- idx grouping (order within group irrelevant -> atomics OK) ----------------
__global__ void k_hzero() { d_cnt[threadIdx.x] = 0; }
__global__ void k_hist() {
    int b = blockIdx.x * 256 + threadIdx.x;
    atomicAdd(&d_cnt[d_idx[b]], 1);
}
__global__ void k_offs() {
    __shared__ int s[128];
    int t = threadIdx.x;
    s[t] = d_cnt[t];
    __syncthreads();
    int acc = 0;
    for (int i = 0; i < t; ++i) acc += s[i];
    d_off[t] = acc;
    d_pos[t] = acc;
}
__global__ void k_scatter() {
    int b = blockIdx.x * 256 + threadIdx.x;
    int p = atomicAdd(&d_pos[d_idx[b]], 1);
    d_blist[p] = b;
}

// ---------------- grouped dot2: grid (128 idx, 2 g-halves), block 256 ----------------
__global__ void k_dot2g(const float* __restrict__ images) {
    __shared__ __half wt[64][132];
    __shared__ float img8[8][512];
    __shared__ int bl_s[8];

    int idx = blockIdx.x, gh = blockIdx.y;
    int c = d_cnt[idx];
    if (c == 0) return;
    int off = d_off[idx];
    int t = threadIdx.x, lane = t & 31, w = t >> 5;

    for (int bc = 0; bc < c; bc += 8) {
        __syncthreads();
        if (t < 8) bl_s[t] = (bc + t < c) ? d_blist[off + bc + t] : -1;
        __syncthreads();
        int nb = (c - bc < 8) ? (c - bc) : 8;
        for (int i = t; i < nb * 512; i += 256)
            img8[i >> 9][i & 511] = images[(size_t)bl_s[i >> 9] * 512 + (i & 511)];

        int myb = bl_s[w];
        float2 a0 = make_float2(0.f, 0.f), a1 = make_float2(0.f, 0.f);
        float a128 = 0.f;

        for (int gt = 0; gt < 4; ++gt) {
            int gbase = (gh * 4 + gt) * 64;
            __syncthreads();
            for (int i = t; i < 64 * 129; i += 256) {
                unsigned g = div129((unsigned)i);
                unsigned j = (unsigned)i - g * 129u;
                wt[g][j] = d_w2h[(size_t)(gbase + g) * KE_ + idx * 129 + j];
            }
            __syncthreads();
            if (myb >= 0) {
                const float* im = img8[w] + gbase;
#pragma unroll 4
                for (int g = 0; g < 64; ++g) {
                    float iv = im[g];
                    const __half2* wr = (const __half2*)&wt[g][0];
                    float2 f0 = __half22float2(wr[lane]);
                    float2 f1 = __half22float2(wr[lane + 32]);
                    a0.x += iv * f0.x; a0.y += iv * f0.y;
                    a1.x += iv * f1.x; a1.y += iv * f1.y;
                    if (lane == 0) a128 += iv * __half2float(wt[g][128]);
                }
            }
        }
        if (myb >= 0) {
            d_dot2p[gh][myb][2 * lane]      = a0.x;
            d_dot2p[gh][myb][2 * lane + 1]  = a0.y;
            d_dot2p[gh][myb][64 + 2 * lane]     = a1.x;
            d_dot2p[gh][myb][64 + 2 * lane + 1] = a1.y;
            if (lane == 0) d_dot2p[gh][myb][128] = a128;
        }
    }
}

// ---------------- softmax3 -> lat2 -> logits4 -> softmax4 ----------------
#define SMEM_L4 ((16641 + 1056 + 1024 + 1056) * 4)
__global__ void k_latlog4(const float* __restrict__ wrec2) {
    extern __shared__ float sm[];
    float* wrec2_s = sm;
    float* xp2_s   = wrec2_s + 16641;
    float* lat2_s  = xp2_s + 1056;
    float* lg4_s   = lat2_s + 1024;

    int t = threadIdx.x, lane = t & 31, w = t >> 5;
    int b0 = blockIdx.x * 8;
    int b = b0 + w;
    int idx = d_idx[b];

    for (int i = t; i < 16512; i += 256)
        wrec2_s[(i >> 7) * 129 + (i & 127)] = wrec2[i];

    {
        const float* cr = d_corr + idx * J_;
        const float* qq = d_q + idx * J_;
        float v[4], v4;
#pragma unroll
        for (int q = 0; q < 4; ++q) {
            int j = q * 32 + lane;
            float dt = d_dot2p[0][b][j] + d_dot2p[1][b][j];
            v[q] = (2.f * (dt - cr[j]) - qq[j]) * (1.f / 512.f);
        }
        if (lane == 0) {
            float dt = d_dot2p[0][b][128] + d_dot2p[1][b][128];
            v4 = (2.f * (dt - cr[128]) - qq[128]) * (1.f / 512.f);
        } else v4 = -INFINITY;
        float m = fmaxf(fmaxf(fmaxf(v[0], v[1]), fmaxf(v[2], v[3])), v4);
        m = wmax(m);
        float e0 = __expf(v[0] - m), e1 = __expf(v[1] - m);
        float e2 = __expf(v[2] - m), e3 = __expf(v[3] - m);
        float e4 = (lane == 0) ? __expf(v4 - m) : 0.f;
        float s = wsum(e0 + e1 + e2 + e3 + e4);
        float inv = 1.f / s;
        xp2_s[w * 132 + lane]      = e0 * inv;
        xp2_s[w * 132 + 32 + lane] = e1 * inv;
        xp2_s[w * 132 + 64 + lane] = e2 * inv;
        xp2_s[w * 132 + 96 + lane] = e3 * inv;
        if (lane == 0) xp2_s[w * 132 + 128] = e4 * inv;
    }
    __syncthreads();

    for (int i = t; i < 1024; i += 256) {
        int bi = i >> 7, e = i & 127;
        float acc = 0.f;
        const float* xp = xp2_s + bi * 132;
#pragma unroll 4
        for (int j = 0; j < 129; ++j) acc += xp[j] * wrec2_s[j * 129 + e];
        lat2_s[i] = acc;
    }
    __syncthreads();

    for (int i = t; i < 1032; i += 256) {
        unsigned bi = div129((unsigned)i);
        unsigned tt = (unsigned)i - bi * 129u;
        float acc = 0.f;
        const float* lt = lat2_s + bi * 128;
#pragma unroll 4
        for (int e = 0; e < 128; ++e) acc += lt[e] * wrec2_s[tt * 129 + e];
        lg4_s[bi * 132 + tt] = (2.f * acc - d_wrec2norm[tt]) * (1.f / 128.f);
    }
    __syncthreads();

    {
        float v[4];
#pragma unroll
        for (int q = 0; q < 4; ++q) v[q] = lg4_s[w * 132 + q * 32 + lane];
        float v4 = (lane == 0) ? lg4_s[w * 132 + 128] : -INFINITY;
        float m = fmaxf(fmaxf(fmaxf(v[0], v[1]), fmaxf(v[2], v[3])), v4);
        m = wmax(m);
        float e0 = __expf(v[0] - m), e1 = __expf(v[1] - m);
        float e2 = __expf(v[2] - m), e3 = __expf(v[3] - m);
        float e4 = (lane == 0) ? __expf(v4 - m) : 0.f;
        float s = wsum(e0 + e1 + e2 + e3 + e4);
        float inv = 1.f / s;
        d_xp2d[b * J_ + lane]      = e0 * inv;
        d_xp2d[b * J_ + 32 + lane] = e1 * inv;
        d_xp2d[b * J_ + 64 + lane] = e2 * inv;
        d_xp2d[b * J_ + 96 + lane] = e3 * inv;
        if (lane == 0) d_xp2d[b * J_ + 128] = e4 * inv;
    }
}

// ---------------- build P (f16) ----------------
__global__ void k_buildP() {
    __shared__ float xp_s[128];
    __shared__ float xp2_s[132];
    int b = blockIdx.x, t = threadIdx.x;
    if (t < 128) xp_s[t] = d_xpd[b * 128 + t];
    if (t < 129) xp2_s[t] = d_xp2d[b * J_ + t];
    __syncthreads();
    __half2* dst = (__half2*)(d_Ph + (size_t)b * KE_);
    for (int i2 = t; i2 < KE_ / 2; i2 += 256) {
        int kj = i2 * 2;
        float v0, v1;
        if (kj < KJ_) {
            unsigned k = div129((unsigned)kj);
            unsigned j = (unsigned)kj - k * 129u;
            float xk = xp_s[k];
            v0 = xk * xp2_s[j];
            v1 = (j < 128) ? xk * xp2_s[j + 1] : xp_s[k + 1] * xp2_s[0];
        } else {
            v0 = xp_s[kj - KJ_];
            v1 = xp_s[kj - KJ_ + 1];
        }
        dst[i2] = __floats2half2_rn(v0, v1);
    }
}

// ---------------- f16 mma.sync GEMM ----------------
__global__ __launch_bounds__(256, 1)
void k_tgemm() {
    extern __shared__ char smem[];
    uint32_t sb = s2u(smem);
    int tid = threadIdx.x;
    int lane = tid & 31, wid = tid >> 5;
    int wm = wid >> 2, wn = wid & 3;
    int row_l = lane >> 2, kq = lane & 3;
    unsigned axorm = (unsigned)row_l << 4;

    int g0 = blockIdx.x * 128, b0 = blockIdx.y * 128, ks = blockIdx.z;
    int cbase = ks * NCH_;
    const char* pbase = (const char*)(d_Ph + (size_t)b0 * KE_);
    const char* wbase = (const char*)(d_w2h + (size_t)g0 * KE_);

    auto fill = [&](int cl, int s) {
        int c = cbase + cl;
        uint32_t asm_ = sb + s * STAGE_B;
        uint32_t bsm = asm_ + 16384;
        const char* psrc = pbase + (size_t)c * 128;
        const char* wsrc = wbase + (size_t)c * 128;
#pragma unroll
        for (int p = 0; p < 4; ++p) {
            int i = tid + p * 256;
            int row = i >> 3;
            int cb = (i & 7) << 4;
            uint32_t sw = SWZ(row * 128 + cb);
            cp16(asm_ + sw, psrc + (size_t)row * (KE_ * 2) + cb);
            cp16(bsm + sw, wsrc + (size_t)row * (KE_ * 2) + cb);
        }
    };

    float acc[4][4][4];
#pragma unroll
    for (int mt = 0; mt < 4; ++mt)
#pragma unroll
        for (int nt = 0; nt < 4; ++nt)
#pragma unroll
            for (int q = 0; q < 4; ++q) acc[mt][nt][q] = 0.f;

#pragma unroll
    for (int cl = 0; cl < GSTAGES - 1; ++cl) {
        fill(cl, cl);
        asm volatile("cp.async.commit_group;" ::: "memory");
    }

    for (int it = 0; it < NCH_; ++it) {
        asm volatile("cp.async.wait_group %0;" :: "n"(GSTAGES - 2) : "memory");
        __syncthreads();

        int cf = it + GSTAGES - 1;
        if (cf < NCH_) fill(cf, cf % GSTAGES);
        asm volatile("cp.async.commit_group;" ::: "memory");

        const char* As = smem + (it % GSTAGES) * STAGE_B;
        const char* Bs = As + 16384;

#pragma unroll
        for (int kst = 0; kst < 4; ++kst) {
            uint32_t af[4][4];
#pragma unroll
            for (int mt = 0; mt < 4; ++mt) {
                unsigned m = wm * 64 + mt * 16 + row_l;
                unsigned base = m * 128 + kst * 32 + kq * 4;
                af[mt][0] = *(const uint32_t*)(As + (base ^ axorm));
                af[mt][1] = *(const uint32_t*)(As + ((base + 8 * 128) ^ axorm));
                af[mt][2] = *(const uint32_t*)(As + ((base + 16) ^ axorm));
                af[mt][3] = *(const uint32_t*)(As + ((base + 8 * 128 + 16) ^ axorm));
            }
            uint32_t bf[4][2];
#pragma unroll
            for (int nt = 0; nt < 4; ++nt) {
                unsigned n = wn * 32 + nt * 8 + row_l;
                unsigned base = n * 128 + kst * 32 + kq * 4;
                bf[nt][0] = *(const uint32_t*)(Bs + (base ^ axorm));
                bf[nt][1] = *(const uint32_t*)(Bs + ((base + 16) ^ axorm));
            }
#pragma unroll
            for (int mt = 0; mt < 4; ++mt)
#pragma unroll
                for (int nt = 0; nt < 4; ++nt)
                    mma_f16(acc[mt][nt], af[mt], bf[nt]);
        }
    }

#pragma unroll
    for (int mt = 0; mt < 4; ++mt) {
#pragma unroll
        for (int nt = 0; nt < 4; ++nt) {
            int grow = b0 + wm * 64 + mt * 16 + row_l;
            int gcol = g0 + wn * 32 + nt * 8 + kq * 2;
            *(float2*)&d_c2[ks][grow][gcol]     = make_float2(acc[mt][nt][0], acc[mt][nt][1]);
            *(float2*)&d_c2[ks][grow + 8][gcol] = make_float2(acc[mt][nt][2], acc[mt][nt][3]);
        }
    }
}

// ---------------- final loss ----------------
__global__ void k_loss(const float* __restrict__ images, float* __restrict__ out) {
    int b = blockIdx.x, t = threadIdx.x;
    float s = 0.f;
    for (int g = t; g < 512; g += 128) {
        float v = d_c2[0][b][g] + d_c2[1][b][g] + d_c2[2][b][g] + d_c2[3][b][g]
                - images[b * 512 + g];
        s += v * v;
    }
    __shared__ float red[128];
    red[t] = s; __syncthreads();
    for (int q = 64; q; q >>= 1) { if (t < q) red[t] += red[t + q]; __syncthreads(); }
    if (t == 0) out[b] = red[0] * (1.f / 512.f);
}

// ---------------- launch ----------------
extern "C" void kernel_launch(void* const* d_in, const int* in_sizes, int n_in,
                              void* d_out, int out_size) {
    const float* images = (const float*)d_in[0];
    const float* wimg   = (const float*)d_in[1];
    const float* wrec   = (const float*)d_in[2];
    const float* wrec2  = (const float*)d_in[3];
    const float* wimg2  = (const float*)d_in[4];
    float* out = (float*)d_out;

    cudaFuncSetAttribute(k_latlog2, cudaFuncAttributeMaxDynamicSharedMemorySize, SMEM_L2);
    cudaFuncSetAttribute(k_latlog4, cudaFuncAttributeMaxDynamicSharedMemorySize, SMEM_L4);
    cudaFuncSetAttribute(k_tgemm,   cudaFuncAttributeMaxDynamicSharedMemorySize, SMEM_G);

    k_prep1<<<dim3(65, 8), 256>>>(wimg, wimg2);
    k_qred<<<65, 256>>>();
    k_norms<<<1, 256>>>(wrec, wrec2);
    k_log1t<<<dim3(8, 4), 256>>>(images, wimg);
    k_latlog2<<<128, 256, SMEM_L2>>>(wrec);
    k_hzero<<<1, 128>>>();
    k_hist<<<4, 256>>>();
    k_offs<<<1, 128>>>();
    k_scatter<<<4, 256>>>();
    k_dot2g<<<dim3(128, 2), 256>>>(images);
    k_latlog4<<<128, 256, SMEM_L4>>>(wrec2);
    k_buildP<<<B_, 256>>>();
    k_tgemm<<<dim3(4, 8, NSPLIT_), 256, SMEM_G>>>();
    k_loss<<<B_, 128>>>(images, out);
}

// round 8
// speedup vs baseline: 13.2666x; 13.2666x over previous
#include <cuda_runtime.h>
#include <cuda_fp16.h>
#include <cstdint>

#define B_   1024
#define G_   512
#define K_   128
#define J_   129
#define KJ_  16512
#define KE_  16640
#define NSPLIT_ 4
#define NCH_ 65
#define GSTAGES 3
#define STAGE_B 32768
#define SMEM_G (GSTAGES * STAGE_B)

// ---------------- device scratch ----------------
__device__ float d_wrecnorm[K_];
__device__ float d_wrec2norm[J_];
__device__ float d_wnorm1[K_];
__device__ float d_q[KJ_];
__device__ float d_corr[KJ_];
__device__ float d_qp[8][KJ_];
__device__ float d_cp[8][KJ_];
__device__ float d_wnp[8][K_];
__device__ float d_lg1p[4][B_][K_];
__device__ float d_xpd[B_ * K_];
__device__ int   d_idx[B_];
__device__ float d_xp2d[B_ * J_];
__device__ float d_dot2[B_ * J_];
__device__ __half d_Ph[(size_t)B_ * KE_];
__device__ __half d_w2h[(size_t)G_ * KE_];
__device__ float d_c2[NSPLIT_][B_][G_];

// ---------------- helpers ----------------
__device__ __forceinline__ uint32_t s2u(const void* p) {
    uint32_t r;
    asm("{ .reg .u64 t; cvta.to.shared.u64 t, %1; cvt.u32.u64 %0, t; }" : "=r"(r) : "l"(p));
    return r;
}
__device__ __forceinline__ void cp16(uint32_t dst, const void* src) {
    asm volatile("cp.async.cg.shared.global [%0], [%1], 16;" :: "r"(dst), "l"(src) : "memory");
}
#define SWZ(o) ((o) ^ ((((unsigned)(o)) >> 3) & 0x70u))

__device__ __forceinline__ void mma_f16(float* c, const uint32_t* a, const uint32_t* b) {
    asm volatile(
        "mma.sync.aligned.m16n8k16.row.col.f32.f16.f16.f32 "
        "{%0,%1,%2,%3}, {%4,%5,%6,%7}, {%8,%9}, {%0,%1,%2,%3};"
        : "+f"(c[0]), "+f"(c[1]), "+f"(c[2]), "+f"(c[3])
        : "r"(a[0]), "r"(a[1]), "r"(a[2]), "r"(a[3]), "r"(b[0]), "r"(b[1]));
}
__device__ __forceinline__ void mma_tf32(float* c, const uint32_t* a, const uint32_t* b) {
    asm volatile(
        "mma.sync.aligned.m16n8k8.row.col.f32.tf32.tf32.f32 "
        "{%0,%1,%2,%3}, {%4,%5,%6,%7}, {%8,%9}, {%0,%1,%2,%3};"
        : "+f"(c[0]), "+f"(c[1]), "+f"(c[2]), "+f"(c[3])
        : "r"(a[0]), "r"(a[1]), "r"(a[2]), "r"(a[3]), "r"(b[0]), "r"(b[1]));
}
__device__ __forceinline__ unsigned div129(unsigned kj) { return (kj * 32515u) >> 22; }
__device__ __forceinline__ float wmax(float v) {
#pragma unroll
    for (int o = 16; o; o >>= 1) v = fmaxf(v, __shfl_xor_sync(~0u, v, o));
    return v;
}
__device__ __forceinline__ float wsum(float v) {
#pragma unroll
    for (int o = 16; o; o >>= 1) v += __shfl_xor_sync(~0u, v, o);
    return v;
}

// ---------------- wimg2 pass ----------------
__global__ void k_prep1(const float* __restrict__ wimg,
                        const float* __restrict__ wimg2) {
    int t = blockIdx.x * 256 + threadIdx.x;
    int gh = blockIdx.y;
    int gbeg = gh * 64;
    if (t < KJ_) {
        unsigned k = div129((unsigned)t);
        float q = 0.f, c = 0.f;
        for (int gg = 0; gg < 64; ++gg) {
            int g = gbeg + gg;
            float v = wimg2[(size_t)g * KJ_ + t];
            float wi = wimg[g * K_ + k];
            q += v * v;
            c += wi * v;
            d_w2h[(size_t)g * KE_ + t] = __float2half(v);
        }
        d_qp[gh][t] = q;
        d_cp[gh][t] = c;
    } else if (t < KE_) {
        int kk = t - KJ_;
        float s = 0.f;
        for (int gg = 0; gg < 64; ++gg) {
            int g = gbeg + gg;
            float v = wimg[g * K_ + kk];
            s += v * v;
            d_w2h[(size_t)g * KE_ + t] = __float2half(v);
        }
        d_wnp[gh][kk] = s;
    }
}

__global__ void k_qred() {
    int t = blockIdx.x * 256 + threadIdx.x;
    if (t < KJ_) {
        float q = 0.f, c = 0.f;
#pragma unroll
        for (int h = 0; h < 8; ++h) { q += d_qp[h][t]; c += d_cp[h][t]; }
        d_q[t] = q;
        d_corr[t] = c;
    } else if (t < KE_) {
        int kk = t - KJ_;
        float s = 0.f;
#pragma unroll
        for (int h = 0; h < 8; ++h) s += d_wnp[h][kk];
        d_wnorm1[kk] = s;
    }
}

__global__ void k_norms(const float* __restrict__ wrec,
                        const float* __restrict__ wrec2) {
    int t = threadIdx.x;
    if (t < K_) {
        float s = 0.f; const float* r = wrec + t * 128;
        for (int e = 0; e < 128; ++e) s += r[e] * r[e];
        d_wrecnorm[t] = s;
    }
    if (t < J_) {
        float s = 0.f; const float* r = wrec2 + t * 128;
        for (int e = 0; e < 128; ++e) s += r[e] * r[e];
        d_wrec2norm[t] = s;
    }
}

// ---------------- logits1 via tf32 mma: grid (8 b-tiles, 4 k-splits) ----------------
__global__ __launch_bounds__(256) void k_log1t(const float* __restrict__ images,
                                               const float* __restrict__ wimg) {
    __shared__ float As[128 * 36];   // images tile [128b x 32g], stride 36
    __shared__ float Bs[32 * 132];   // wimg tile  [32g x 128k], stride 132

    int tid = threadIdx.x, lane = tid & 31, wid = tid >> 5;
    int wm = wid >> 2, wn = wid & 3;
    int row_l = lane >> 2, kq = lane & 3;
    int b0 = blockIdx.x * 128, ks = blockIdx.y;
    uint32_t asb = s2u(As), bsb = s2u(Bs);

    float acc[4][4][4];
#pragma unroll
    for (int mt = 0; mt < 4; ++mt)
#pragma unroll
        for (int nt = 0; nt < 4; ++nt)
#pragma unroll
            for (int q = 0; q < 4; ++q) acc[mt][nt][q] = 0.f;

    for (int c = 0; c < 4; ++c) {
        int g0 = ks * 128 + c * 32;
#pragma unroll
        for (int p = 0; p < 4; ++p) {
            int i = tid + p * 256;
            int row = i >> 3, c4 = (i & 7) << 2;
            cp16(asb + (row * 36 + c4) * 4, images + (size_t)(b0 + row) * 512 + g0 + c4);
        }
#pragma unroll
        for (int p = 0; p < 4; ++p) {
            int i = tid + p * 256;
            int row = i >> 5, c4 = (i & 31) << 2;
            cp16(bsb + (row * 132 + c4) * 4, wimg + (size_t)(g0 + row) * 128 + c4);
        }
        asm volatile("cp.async.commit_group;" ::: "memory");
        asm volatile("cp.async.wait_group 0;" ::: "memory");
        __syncthreads();

#pragma unroll
        for (int kst = 0; kst < 4; ++kst) {
            uint32_t af[4][4];
#pragma unroll
            for (int mt = 0; mt < 4; ++mt) {
                int m = wm * 64 + mt * 16 + row_l;
                const float* ap = As + m * 36 + kst * 8 + kq;
                af[mt][0] = __float_as_uint(ap[0]);
                af[mt][1] = __float_as_uint(ap[8 * 36]);
                af[mt][2] = __float_as_uint(ap[4]);
                af[mt][3] = __float_as_uint(ap[8 * 36 + 4]);
            }
            uint32_t bf[4][2];
#pragma unroll
            for (int nt = 0; nt < 4; ++nt) {
                int n = wn * 32 + nt * 8 + row_l;
                const float* bp = Bs + (kst * 8 + kq) * 132 + n;
                bf[nt][0] = __float_as_uint(bp[0]);
                bf[nt][1] = __float_as_uint(bp[4 * 132]);
            }
#pragma unroll
            for (int mt = 0; mt < 4; ++mt)
#pragma unroll
                for (int nt = 0; nt < 4; ++nt)
                    mma_tf32(acc[mt][nt], af[mt], bf[nt]);
        }
        __syncthreads();
    }

#pragma unroll
    for (int mt = 0; mt < 4; ++mt)
#pragma unroll
        for (int nt = 0; nt < 4; ++nt) {
            int row = b0 + wm * 64 + mt * 16 + row_l;
            int col = wn * 32 + nt * 8 + kq * 2;
            *(float2*)&d_lg1p[ks][row][col]     = make_float2(acc[mt][nt][0], acc[mt][nt][1]);
            *(float2*)&d_lg1p[ks][row + 8][col] = make_float2(acc[mt][nt][2], acc[mt][nt][3]);
        }
}

// ---------------- softmax1 -> lat -> logits2 -> softmax2+argmax ----------------
#define SMEM_L2 ((16512 + 1024 + 1024 + 1024) * 4)
__global__ void k_latlog2(const float* __restrict__ wrec) {
    extern __shared__ float sm[];
    float* wrec_s = sm;
    float* xp1_s  = wrec_s + 16512;
    float* lat_s  = xp1_s + 1024;
    float* lg2_s  = lat_s + 1024;

    int t = threadIdx.x, lane = t & 31, w = t >> 5;
    int b0 = blockIdx.x * 8;
    int b = b0 + w;

    for (int i = t; i < 16384; i += 256)
        wrec_s[(i >> 7) * 129 + (i & 127)] = wrec[i];

    {
        float v[4];
#pragma unroll
        for (int q = 0; q < 4; ++q) {
            int k = q * 32 + lane;
            float d = d_lg1p[0][b][k] + d_lg1p[1][b][k] + d_lg1p[2][b][k] + d_lg1p[3][b][k];
            v[q] = (2.f * d - d_wnorm1[k]) * (1.f / 512.f);
        }
        float m = fmaxf(fmaxf(v[0], v[1]), fmaxf(v[2], v[3]));
        m = wmax(m);
        float e0 = __expf(v[0] - m), e1 = __expf(v[1] - m);
        float e2 = __expf(v[2] - m), e3 = __expf(v[3] - m);
        float s = wsum(e0 + e1 + e2 + e3);
        float inv = 1.f / s;
        xp1_s[w * 128 + lane]      = e0 * inv;
        xp1_s[w * 128 + 32 + lane] = e1 * inv;
        xp1_s[w * 128 + 64 + lane] = e2 * inv;
        xp1_s[w * 128 + 96 + lane] = e3 * inv;
    }
    __syncthreads();

    for (int i = t; i < 1024; i += 256) {
        int bi = i >> 7, e = i & 127;
        float acc = 0.f;
        const float* xp = xp1_s + bi * 128;
#pragma unroll 4
        for (int k = 0; k < 128; ++k) acc += xp[k] * wrec_s[k * 129 + e];
        lat_s[i] = acc;
    }
    __syncthreads();

    for (int i = t; i < 1024; i += 256) {
        int bi = i >> 7, tt = i & 127;
        float acc = 0.f;
        const float* lt = lat_s + bi * 128;
#pragma unroll 4
        for (int e = 0; e < 128; ++e) acc += lt[e] * wrec_s[tt * 129 + e];
        lg2_s[i] = (2.f * acc - d_wrecnorm[tt]) * (1.f / 128.f);
    }
    __syncthreads();

    {
        float v[4];
#pragma unroll
        for (int q = 0; q < 4; ++q) v[q] = lg2_s[w * 128 + q * 32 + lane];
        float bv = v[0]; int bk = lane;
#pragma unroll
        for (int q = 1; q < 4; ++q)
            if (v[q] > bv) { bv = v[q]; bk = q * 32 + lane; }
#pragma unroll
        for (int o = 16; o; o >>= 1) {
            float ov = __shfl_xor_sync(~0u, bv, o);
            int   ok = __shfl_xor_sync(~0u, bk, o);
            if (ov > bv || (ov == bv && ok < bk)) { bv = ov; bk = ok; }
        }
        if (lane == 0) d_idx[b] = bk;
        float m = bv;
        float e0 = __expf(v[0] - m), e1 = __expf(v[1] - m);
        float e2 = __expf(v[2] - m), e3 = __expf(v[3] - m);
        float s = wsum(e0 + e1 + e2 + e3);
        float inv = 1.f / s;
        d_xpd[b * 128 + lane]      = e0 * inv;
        d_xpd[b * 128 + 32 + lane] = e1 * inv;
        d_xpd[b * 128 + 64 + lane] = e2 * inv;
        d_xpd[b * 128 + 96 + lane] = e3 * inv;
    }
}

// ---------------- dot2: per-b, g-parallel coalesced (load-balanced) ----------------
__global__ void k_dot2(const float* __restrict__ images) {
    __shared__ float img_s[512];
    __shared__ float part[8][136];
    int b = blockIdx.x, t = threadIdx.x, lane = t & 31, w = t >> 5;
    for (int i = t; i < 512; i += 256) img_s[i] = images[b * 512 + i];
    __syncthreads();
    int idx = d_idx[b];
    const __half* colb = d_w2h + (size_t)idx * 129;
    float a0 = 0.f, a1 = 0.f, a2 = 0.f, a3 = 0.f, a4 = 0.f;
    for (int g = w; g < 512; g += 8) {
        float iv = img_s[g];
        const __half* rp = colb + (size_t)g * KE_;
        a0 += iv * __half2float(rp[lane]);
        a1 += iv * __half2float(rp[lane + 32]);
        a2 += iv * __half2float(rp[lane + 64]);
        a3 += iv * __half2float(rp[lane + 96]);
        if (lane == 0) a4 += iv * __half2float(rp[128]);
    }
    part[w][lane] = a0; part[w][lane + 32] = a1;
    part[w][lane + 64] = a2; part[w][lane + 96] = a3;
    if (lane == 0) part[w][128] = a4;
    __syncthreads();
    if (t < 129) {
        float s = 0.f;
#pragma unroll
        for (int ww = 0; ww < 8; ++ww) s += part[ww][t];
        d_dot2[b * J_ + t] = s;
    }
}

// ---------------- softmax3 -> lat2 -> logits4 -> softmax4 ----------------
#define SMEM_L4 ((16641 + 1056 + 1024 + 1056) * 4)
__global__ void k_latlog4(const float* __restrict__ wrec2) {
    extern __shared__ float sm[];
    float* wrec2_s = sm;
    float* xp2_s   = wrec2_s + 16641;
    float* lat2_s  = xp2_s + 1056;
    float* lg4_s   = lat2_s + 1024;

    int t = threadIdx.x, lane = t & 31, w = t >> 5;
    int b0 = blockIdx.x * 8;
    int b = b0 + w;
    int idx = d_idx[b];

    for (int i = t; i < 16512; i += 256)
        wrec2_s[(i >> 7) * 129 + (i & 127)] = wrec2[i];

    {
        const float* dt = d_dot2 + b * J_;
        const float* cr = d_corr + idx * J_;
        const float* qq = d_q + idx * J_;
        float v[4], v4;
#pragma unroll
        for (int q = 0; q < 4; ++q) {
            int j = q * 32 + lane;
            v[q] = (2.f * (dt[j] - cr[j]) - qq[j]) * (1.f / 512.f);
        }
        v4 = (lane == 0) ? (2.f * (dt[128] - cr[128]) - qq[128]) * (1.f / 512.f) : -INFINITY;
        float m = fmaxf(fmaxf(fmaxf(v[0], v[1]), fmaxf(v[2], v[3])), v4);
        m = wmax(m);
        float e0 = __expf(v[0] - m), e1 = __expf(v[1] - m);
        float e2 = __expf(v[2] - m), e3 = __expf(v[3] - m);
        float e4 = (lane == 0) ? __expf(v4 - m) : 0.f;
        float s = wsum(e0 + e1 + e2 + e3 + e4);
        float inv = 1.f / s;
        xp2_s[w * 132 + lane]      = e0 * inv;
        xp2_s[w * 132 + 32 + lane] = e1 * inv;
        xp2_s[w * 132 + 64 + lane] = e2 * inv;
        xp2_s[w * 132 + 96 + lane] = e3 * inv;
        if (lane == 0) xp2_s[w * 132 + 128] = e4 * inv;
    }
    __syncthreads();

    for (int i = t; i < 1024; i += 256) {
        int bi = i >> 7, e = i & 127;
        float acc = 0.f;
        const float* xp = xp2_s + bi * 132;
#pragma unroll 4
        for (int j = 0; j < 129; ++j) acc += xp[j] * wrec2_s[j * 129 + e];
        lat2_s[i] = acc;
    }
    __syncthreads();

    for (int i = t; i < 1032; i += 256) {
        unsigned bi = div129((unsigned)i);
        unsigned tt = (unsigned)i - bi * 129u;
        float acc = 0.f;
        const float* lt = lat2_s + bi * 128;
#pragma unroll 4
        for (int e = 0; e < 128; ++e) acc += lt[e] * wrec2_s[tt * 129 + e];
        lg4_s[bi * 132 + tt] = (2.f * acc - d_wrec2norm[tt]) * (1.f / 128.f);
    }
    __syncthreads();

    {
        float v[4];
#pragma unroll
        for (int q = 0; q < 4; ++q) v[q] = lg4_s[w * 132 + q * 32 + lane];
        float v4 = (lane == 0) ? lg4_s[w * 132 + 128] : -INFINITY;
        float m = fmaxf(fmaxf(fmaxf(v[0], v[1]), fmaxf(v[2], v[3])), v4);
        m = wmax(m);
        float e0 = __expf(v[0] - m), e1 = __expf(v[1] - m);
        float e2 = __expf(v[2] - m), e3 = __expf(v[3] - m);
        float e4 = (lane == 0) ? __expf(v4 - m) : 0.f;
        float s = wsum(e0 + e1 + e2 + e3 + e4);
        float inv = 1.f / s;
        d_xp2d[b * J_ + lane]      = e0 * inv;
        d_xp2d[b * J_ + 32 + lane] = e1 * inv;
        d_xp2d[b * J_ + 64 + lane] = e2 * inv;
        d_xp2d[b * J_ + 96 + lane] = e3 * inv;
        if (lane == 0) d_xp2d[b * J_ + 128] = e4 * inv;
    }
}

// ---------------- build P (f16) ----------------
__global__ void k_buildP() {
    __shared__ float xp_s[128];
    __shared__ float xp2_s[132];
    int b = blockIdx.x, t = threadIdx.x;
    if (t < 128) xp_s[t] = d_xpd[b * 128 + t];
    if (t < 129) xp2_s[t] = d_xp2d[b * J_ + t];
    __syncthreads();
    __half2* dst = (__half2*)(d_Ph + (size_t)b * KE_);
    for (int i2 = t; i2 < KE_ / 2; i2 += 256) {
        int kj = i2 * 2;
        float v0, v1;
        if (kj < KJ_) {
            unsigned k = div129((unsigned)kj);
            unsigned j = (unsigned)kj - k * 129u;
            float xk = xp_s[k];
            v0 = xk * xp2_s[j];
            v1 = (j < 128) ? xk * xp2_s[j + 1] : xp_s[k + 1] * xp2_s[0];
        } else {
            v0 = xp_s[kj - KJ_];
            v1 = xp_s[kj - KJ_ + 1];
        }
        dst[i2] = __floats2half2_rn(v0, v1);
    }
}

// ---------------- f16 mma.sync GEMM ----------------
__global__ __launch_bounds__(256, 1)
void k_tgemm() {
    extern __shared__ char smem[];
    uint32_t sb = s2u(smem);
    int tid = threadIdx.x;
    int lane = tid & 31, wid = tid >> 5;
    int wm = wid >> 2, wn = wid & 3;
    int row_l = lane >> 2, kq = lane & 3;
    unsigned axorm = (unsigned)row_l << 4;

    int g0 = blockIdx.x * 128, b0 = blockIdx.y * 128, ks = blockIdx.z;
    int cbase = ks * NCH_;
    const char* pbase = (const char*)(d_Ph + (size_t)b0 * KE_);
    const char* wbase = (const char*)(d_w2h + (size_t)g0 * KE_);

    auto fill = [&](int cl, int s) {
        int c = cbase + cl;
        uint32_t asm_ = sb + s * STAGE_B;
        uint32_t bsm = asm_ + 16384;
        const char* psrc = pbase + (size_t)c * 128;
        const char* wsrc = wbase + (size_t)c * 128;
#pragma unroll
        for (int p = 0; p < 4; ++p) {
            int i = tid + p * 256;
            int row = i >> 3;
            int cb = (i & 7) << 4;
            uint32_t sw = SWZ(row * 128 + cb);
            cp16(asm_ + sw, psrc + (size_t)row * (KE_ * 2) + cb);
            cp16(bsm + sw, wsrc + (size_t)row * (KE_ * 2) + cb);
        }
    };

    float acc[4][4][4];
#pragma unroll
    for (int mt = 0; mt < 4; ++mt)
#pragma unroll
        for (int nt = 0; nt < 4; ++nt)
#pragma unroll
            for (int q = 0; q < 4; ++q) acc[mt][nt][q] = 0.f;

#pragma unroll
    for (int cl = 0; cl < GSTAGES - 1; ++cl) {
        fill(cl, cl);
        asm volatile("cp.async.commit_group;" ::: "memory");
    }

    for (int it = 0; it < NCH_; ++it) {
        asm volatile("cp.async.wait_group %0;" :: "n"(GSTAGES - 2) : "memory");
        __syncthreads();

        int cf = it + GSTAGES - 1;
        if (cf < NCH_) fill(cf, cf % GSTAGES);
        asm volatile("cp.async.commit_group;" ::: "memory");

        const char* As = smem + (it % GSTAGES) * STAGE_B;
        const char* Bs = As + 16384;

#pragma unroll
        for (int kst = 0; kst < 4; ++kst) {
            uint32_t af[4][4];
#pragma unroll
            for (int mt = 0; mt < 4; ++mt) {
                unsigned m = wm * 64 + mt * 16 + row_l;
                unsigned base = m * 128 + kst * 32 + kq * 4;
                af[mt][0] = *(const uint32_t*)(As + (base ^ axorm));
                af[mt][1] = *(const uint32_t*)(As + ((base + 8 * 128) ^ axorm));
                af[mt][2] = *(const uint32_t*)(As + ((base + 16) ^ axorm));
                af[mt][3] = *(const uint32_t*)(As + ((base + 8 * 128 + 16) ^ axorm));
            }
            uint32_t bf[4][2];
#pragma unroll
            for (int nt = 0; nt < 4; ++nt) {
                unsigned n = wn * 32 + nt * 8 + row_l;
                unsigned base = n * 128 + kst * 32 + kq * 4;
                bf[nt][0] = *(const uint32_t*)(Bs + (base ^ axorm));
                bf[nt][1] = *(const uint32_t*)(Bs + ((base + 16) ^ axorm));
            }
#pragma unroll
            for (int mt = 0; mt < 4; ++mt)
#pragma unroll
                for (int nt = 0; nt < 4; ++nt)
                    mma_f16(acc[mt][nt], af[mt], bf[nt]);
        }
    }

#pragma unroll
    for (int mt = 0; mt < 4; ++mt) {
#pragma unroll
        for (int nt = 0; nt < 4; ++nt) {
            int grow = b0 + wm * 64 + mt * 16 + row_l;
            int gcol = g0 + wn * 32 + nt * 8 + kq * 2;
            *(float2*)&d_c2[ks][grow][gcol]     = make_float2(acc[mt][nt][0], acc[mt][nt][1]);
            *(float2*)&d_c2[ks][grow + 8][gcol] = make_float2(acc[mt][nt][2], acc[mt][nt][3]);
        }
    }
}

// ---------------- final loss ----------------
__global__ void k_loss(const float* __restrict__ images, float* __restrict__ out) {
    int b = blockIdx.x, t = threadIdx.x;
    float s = 0.f;
    for (int g = t; g < 512; g += 128) {
        float v = d_c2[0][b][g] + d_c2[1][b][g] + d_c2[2][b][g] + d_c2[3][b][g]
                - images[b * 512 + g];
        s += v * v;
    }
    __shared__ float red[128];
    red[t] = s; __syncthreads();
    for (int q = 64; q; q >>= 1) { if (t < q) red[t] += red[t + q]; __syncthreads(); }
    if (t == 0) out[b] = red[0] * (1.f / 512.f);
}

// ---------------- launch ----------------
extern "C" void kernel_launch(void* const* d_in, const int* in_sizes, int n_in,
                              void* d_out, int out_size) {
    const float* images = (const float*)d_in[0];
    const float* wimg   = (const float*)d_in[1];
    const float* wrec   = (const float*)d_in[2];
    const float* wrec2  = (const float*)d_in[3];
    const float* wimg2  = (const float*)d_in[4];
    float* out = (float*)d_out;

    cudaFuncSetAttribute(k_latlog2, cudaFuncAttributeMaxDynamicSharedMemorySize, SMEM_L2);
    cudaFuncSetAttribute(k_latlog4, cudaFuncAttributeMaxDynamicSharedMemorySize, SMEM_L4);
    cudaFuncSetAttribute(k_tgemm,   cudaFuncAttributeMaxDynamicSharedMemorySize, SMEM_G);

    k_prep1<<<dim3(65, 8), 256>>>(wimg, wimg2);
    k_qred<<<65, 256>>>();
    k_norms<<<1, 256>>>(wrec, wrec2);
    k_log1t<<<dim3(8, 4), 256>>>(images, wimg);
    k_latlog2<<<128, 256, SMEM_L2>>>(wrec);
    k_dot2<<<B_, 256>>>(images);
    k_latlog4<<<128, 256, SMEM_L4>>>(wrec2);
    k_buildP<<<B_, 256>>>();
    k_tgemm<<<dim3(4, 8, NSPLIT_), 256, SMEM_G>>>();
    k_loss<<<B_, 128>>>(images, out);
}

// round 9
// speedup vs baseline: 13.4093x; 1.0108x over previous
#include <cuda_runtime.h>
#include <cuda_fp16.h>
#include <cstdint>

#define B_   1024
#define G_   512
#define K_   128
#define J_   129
#define KJ_  16512
#define KE_  16640
#define KE2_ 16896          // padded K (264 chunks of 64); pad region stays zero
#define NSPLIT_ 8
#define NCH_ 33             // 264 / 8
#define GSTAGES 3
#define STAGE_B 32768
#define SMEM_G (GSTAGES * STAGE_B)
#define NLS_ 16             // log1t k-splits

// ---------------- device scratch ----------------
__device__ float d_wrecnorm[K_];
__device__ float d_wrec2norm[J_];
__device__ float d_wnorm1[K_];
__device__ float d_q[KJ_];
__device__ float d_corr[KJ_];
__device__ float d_qp[8][KJ_];
__device__ float d_cp[8][KJ_];
__device__ float d_wnp[8][K_];
__device__ float d_lg1p[NLS_][B_][K_];
__device__ float d_xpd[B_ * K_];
__device__ int   d_idx[B_];
__device__ float d_xp2d[B_ * J_];
__device__ float d_dot2[B_ * J_];
__device__ __half d_Ph[(size_t)B_ * KE2_];    // tail [KE_,KE2_) never written -> zero
__device__ __half d_w2h[(size_t)G_ * KE2_];   // tail zero
__device__ float d_c2[NSPLIT_][B_][G_];

// ---------------- helpers ----------------
__device__ __forceinline__ uint32_t s2u(const void* p) {
    uint32_t r;
    asm("{ .reg .u64 t; cvta.to.shared.u64 t, %1; cvt.u32.u64 %0, t; }" : "=r"(r) : "l"(p));
    return r;
}
__device__ __forceinline__ void cp16(uint32_t dst, const void* src) {
    asm volatile("cp.async.cg.shared.global [%0], [%1], 16;" :: "r"(dst), "l"(src) : "memory");
}
#define SWZ(o) ((o) ^ ((((unsigned)(o)) >> 3) & 0x70u))

__device__ __forceinline__ void mma_f16(float* c, const uint32_t* a, const uint32_t* b) {
    asm volatile(
        "mma.sync.aligned.m16n8k16.row.col.f32.f16.f16.f32 "
        "{%0,%1,%2,%3}, {%4,%5,%6,%7}, {%8,%9}, {%0,%1,%2,%3};"
        : "+f"(c[0]), "+f"(c[1]), "+f"(c[2]), "+f"(c[3])
        : "r"(a[0]), "r"(a[1]), "r"(a[2]), "r"(a[3]), "r"(b[0]), "r"(b[1]));
}
__device__ __forceinline__ void mma_tf32(float* c, const uint32_t* a, const uint32_t* b) {
    asm volatile(
        "mma.sync.aligned.m16n8k8.row.col.f32.tf32.tf32.f32 "
        "{%0,%1,%2,%3}, {%4,%5,%6,%7}, {%8,%9}, {%0,%1,%2,%3};"
        : "+f"(c[0]), "+f"(c[1]), "+f"(c[2]), "+f"(c[3])
        : "r"(a[0]), "r"(a[1]), "r"(a[2]), "r"(a[3]), "r"(b[0]), "r"(b[1]));
}
__device__ __forceinline__ unsigned div129(unsigned kj) { return (kj * 32515u) >> 22; }
__device__ __forceinline__ float wmax(float v) {
#pragma unroll
    for (int o = 16; o; o >>= 1) v = fmaxf(v, __shfl_xor_sync(~0u, v, o));
    return v;
}
__device__ __forceinline__ float wsum(float v) {
#pragma unroll
    for (int o = 16; o; o >>= 1) v += __shfl_xor_sync(~0u, v, o);
    return v;
}

// ---------------- wimg2 pass ----------------
__global__ void k_prep1(const float* __restrict__ wimg,
                        const float* __restrict__ wimg2) {
    int t = blockIdx.x * 256 + threadIdx.x;
    int gh = blockIdx.y;
    int gbeg = gh * 64;
    if (t < KJ_) {
        unsigned k = div129((unsigned)t);
        float q = 0.f, c = 0.f;
        for (int gg = 0; gg < 64; ++gg) {
            int g = gbeg + gg;
            float v = wimg2[(size_t)g * KJ_ + t];
            float wi = wimg[g * K_ + k];
            q += v * v;
            c += wi * v;
            d_w2h[(size_t)g * KE2_ + t] = __float2half(v);
        }
        d_qp[gh][t] = q;
        d_cp[gh][t] = c;
    } else if (t < KE_) {
        int kk = t - KJ_;
        float s = 0.f;
        for (int gg = 0; gg < 64; ++gg) {
            int g = gbeg + gg;
            float v = wimg[g * K_ + kk];
            s += v * v;
            d_w2h[(size_t)g * KE2_ + t] = __float2half(v);
        }
        d_wnp[gh][kk] = s;
    }
}

// grid 66: blocks 0..64 reduce partials, block 65 computes wrec/wrec2 norms
__global__ void k_qred(const float* __restrict__ wrec,
                       const float* __restrict__ wrec2) {
    if (blockIdx.x == 65) {
        int t = threadIdx.x;
        if (t < K_) {
            float s = 0.f; const float* r = wrec + t * 128;
            for (int e = 0; e < 128; ++e) s += r[e] * r[e];
            d_wrecnorm[t] = s;
        }
        if (t < J_) {
            float s = 0.f; const float* r = wrec2 + t * 128;
            for (int e = 0; e < 128; ++e) s += r[e] * r[e];
            d_wrec2norm[t] = s;
        }
        return;
    }
    int t = blockIdx.x * 256 + threadIdx.x;
    if (t < KJ_) {
        float q = 0.f, c = 0.f;
#pragma unroll
        for (int h = 0; h < 8; ++h) { q += d_qp[h][t]; c += d_cp[h][t]; }
        d_q[t] = q;
        d_corr[t] = c;
    } else if (t < KE_) {
        int kk = t - KJ_;
        float s = 0.f;
#pragma unroll
        for (int h = 0; h < 8; ++h) s += d_wnp[h][kk];
        d_wnorm1[kk] = s;
    }
}

// ---------------- logits1 via tf32 mma: grid (8 b-tiles, 16 k-splits) ----------------
__global__ __launch_bounds__(256) void k_log1t(const float* __restrict__ images,
                                               const float* __restrict__ wimg) {
    __shared__ float As[128 * 36];   // images tile [128b x 32g], stride 36
    __shared__ float Bs[32 * 132];   // wimg tile  [32g x 128k], stride 132

    int tid = threadIdx.x, lane = tid & 31, wid = tid >> 5;
    int wm = wid >> 2, wn = wid & 3;
    int row_l = lane >> 2, kq = lane & 3;
    int b0 = blockIdx.x * 128, ks = blockIdx.y;
    int g0 = ks * 32;
    uint32_t asb = s2u(As), bsb = s2u(Bs);

    float acc[4][4][4];
#pragma unroll
    for (int mt = 0; mt < 4; ++mt)
#pragma unroll
        for (int nt = 0; nt < 4; ++nt)
#pragma unroll
            for (int q = 0; q < 4; ++q) acc[mt][nt][q] = 0.f;

#pragma unroll
    for (int p = 0; p < 4; ++p) {
        int i = tid + p * 256;
        int row = i >> 3, c4 = (i & 7) << 2;
        cp16(asb + (row * 36 + c4) * 4, images + (size_t)(b0 + row) * 512 + g0 + c4);
    }
#pragma unroll
    for (int p = 0; p < 4; ++p) {
        int i = tid + p * 256;
        int row = i >> 5, c4 = (i & 31) << 2;
        cp16(bsb + (row * 132 + c4) * 4, wimg + (size_t)(g0 + row) * 128 + c4);
    }
    asm volatile("cp.async.commit_group;" ::: "memory");
    asm volatile("cp.async.wait_group 0;" ::: "memory");
    __syncthreads();

#pragma unroll
    for (int kst = 0; kst < 4; ++kst) {
        uint32_t af[4][4];
#pragma unroll
        for (int mt = 0; mt < 4; ++mt) {
            int m = wm * 64 + mt * 16 + row_l;
            const float* ap = As + m * 36 + kst * 8 + kq;
            af[mt][0] = __float_as_uint(ap[0]);
            af[mt][1] = __float_as_uint(ap[8 * 36]);
            af[mt][2] = __float_as_uint(ap[4]);
            af[mt][3] = __float_as_uint(ap[8 * 36 + 4]);
        }
        uint32_t bf[4][2];
#pragma unroll
        for (int nt = 0; nt < 4; ++nt) {
            int n = wn * 32 + nt * 8 + row_l;
            const float* bp = Bs + (kst * 8 + kq) * 132 + n;
            bf[nt][0] = __float_as_uint(bp[0]);
            bf[nt][1] = __float_as_uint(bp[4 * 132]);
        }
#pragma unroll
        for (int mt = 0; mt < 4; ++mt)
#pragma unroll
            for (int nt = 0; nt < 4; ++nt)
                mma_tf32(acc[mt][nt], af[mt], bf[nt]);
    }

#pragma unroll
    for (int mt = 0; mt < 4; ++mt)
#pragma unroll
        for (int nt = 0; nt < 4; ++nt) {
            int row = b0 + wm * 64 + mt * 16 + row_l;
            int col = wn * 32 + nt * 8 + kq * 2;
            *(float2*)&d_lg1p[ks][row][col]     = make_float2(acc[mt][nt][0], acc[mt][nt][1]);
            *(float2*)&d_lg1p[ks][row + 8][col] = make_float2(acc[mt][nt][2], acc[mt][nt][3]);
        }
}

// ---------------- softmax1 -> lat -> logits2 -> softmax2+argmax ----------------
#define SMEM_L2 ((16512 + 1024 + 1024 + 1024) * 4)
__global__ void k_latlog2(const float* __restrict__ wrec) {
    extern __shared__ float sm[];
    float* wrec_s = sm;
    float* xp1_s  = wrec_s + 16512;
    float* lat_s  = xp1_s + 1024;
    float* lg2_s  = lat_s + 1024;

    int t = threadIdx.x, lane = t & 31, w = t >> 5;
    int b0 = blockIdx.x * 8;
    int b = b0 + w;

    for (int i = t; i < 16384; i += 256)
        wrec_s[(i >> 7) * 129 + (i & 127)] = wrec[i];

    {
        float v[4];
#pragma unroll
        for (int q = 0; q < 4; ++q) {
            int k = q * 32 + lane;
            float d = 0.f;
#pragma unroll
            for (int h = 0; h < NLS_; ++h) d += d_lg1p[h][b][k];
            v[q] = (2.f * d - d_wnorm1[k]) * (1.f / 512.f);
        }
        float m = fmaxf(fmaxf(v[0], v[1]), fmaxf(v[2], v[3]));
        m = wmax(m);
        float e0 = __expf(v[0] - m), e1 = __expf(v[1] - m);
        float e2 = __expf(v[2] - m), e3 = __expf(v[3] - m);
        float s = wsum(e0 + e1 + e2 + e3);
        float inv = 1.f / s;
        xp1_s[w * 128 + lane]      = e0 * inv;
        xp1_s[w * 128 + 32 + lane] = e1 * inv;
        xp1_s[w * 128 + 64 + lane] = e2 * inv;
        xp1_s[w * 128 + 96 + lane] = e3 * inv;
    }
    __syncthreads();

    for (int i = t; i < 1024; i += 256) {
        int bi = i >> 7, e = i & 127;
        float acc = 0.f;
        const float* xp = xp1_s + bi * 128;
#pragma unroll 4
        for (int k = 0; k < 128; ++k) acc += xp[k] * wrec_s[k * 129 + e];
        lat_s[i] = acc;
    }
    __syncthreads();

    for (int i = t; i < 1024; i += 256) {
        int bi = i >> 7, tt = i & 127;
        float acc = 0.f;
        const float* lt = lat_s + bi * 128;
#pragma unroll 4
        for (int e = 0; e < 128; ++e) acc += lt[e] * wrec_s[tt * 129 + e];
        lg2_s[i] = (2.f * acc - d_wrecnorm[tt]) * (1.f / 128.f);
    }
    __syncthreads();

    {
        float v[4];
#pragma unroll
        for (int q = 0; q < 4; ++q) v[q] = lg2_s[w * 128 + q * 32 + lane];
        float bv = v[0]; int bk = lane;
#pragma unroll
        for (int q = 1; q < 4; ++q)
            if (v[q] > bv) { bv = v[q]; bk = q * 32 + lane; }
#pragma unroll
        for (int o = 16; o; o >>= 1) {
            float ov = __shfl_xor_sync(~0u, bv, o);
            int   ok = __shfl_xor_sync(~0u, bk, o);
            if (ov > bv || (ov == bv && ok < bk)) { bv = ov; bk = ok; }
        }
        if (lane == 0) d_idx[b] = bk;
        float m = bv;
        float e0 = __expf(v[0] - m), e1 = __expf(v[1] - m);
        float e2 = __expf(v[2] - m), e3 = __expf(v[3] - m);
        float s = wsum(e0 + e1 + e2 + e3);
        float inv = 1.f / s;
        d_xpd[b * 128 + lane]      = e0 * inv;
        d_xpd[b * 128 + 32 + lane] = e1 * inv;
        d_xpd[b * 128 + 64 + lane] = e2 * inv;
        d_xpd[b * 128 + 96 + lane] = e3 * inv;
    }
}

// ---------------- dot2: per-b, g-parallel coalesced ----------------
__global__ void k_dot2(const float* __restrict__ images) {
    __shared__ float img_s[512];
    __shared__ float part[8][136];
    int b = blockIdx.x, t = threadIdx.x, lane = t & 31, w = t >> 5;
    for (int i = t; i < 512; i += 256) img_s[i] = images[b * 512 + i];
    __syncthreads();
    int idx = d_idx[b];
    const __half* colb = d_w2h + (size_t)idx * 129;
    float a0 = 0.f, a1 = 0.f, a2 = 0.f, a3 = 0.f, a4 = 0.f;
    for (int g = w; g < 512; g += 8) {
        float iv = img_s[g];
        const __half* rp = colb + (size_t)g * KE2_;
        a0 += iv * __half2float(rp[lane]);
        a1 += iv * __half2float(rp[lane + 32]);
        a2 += iv * __half2float(rp[lane + 64]);
        a3 += iv * __half2float(rp[lane + 96]);
        if (lane == 0) a4 += iv * __half2float(rp[128]);
    }
    part[w][lane] = a0; part[w][lane + 32] = a1;
    part[w][lane + 64] = a2; part[w][lane + 96] = a3;
    if (lane == 0) part[w][128] = a4;
    __syncthreads();
    if (t < 129) {
        float s = 0.f;
#pragma unroll
        for (int ww = 0; ww < 8; ++ww) s += part[ww][t];
        d_dot2[b * J_ + t] = s;
    }
}

// ---------------- softmax3 -> lat2 -> logits4 -> softmax4 ----------------
#define SMEM_L4 ((16641 + 1056 + 1024 + 1056) * 4)
__global__ void k_latlog4(const float* __restrict__ wrec2) {
    extern __shared__ float sm[];
    float* wrec2_s = sm;
    float* xp2_s   = wrec2_s + 16641;
    float* lat2_s  = xp2_s + 1056;
    float* lg4_s   = lat2_s + 1024;

    int t = threadIdx.x, lane = t & 31, w = t >> 5;
    int b0 = blockIdx.x * 8;
    int b = b0 + w;
    int idx = d_idx[b];

    for (int i = t; i < 16512; i += 256)
        wrec2_s[(i >> 7) * 129 + (i & 127)] = wrec2[i];

    {
        const float* dt = d_dot2 + b * J_;
        const float* cr = d_corr + idx * J_;
        const float* qq = d_q + idx * J_;
        float v[4], v4;
#pragma unroll
        for (int q = 0; q < 4; ++q) {
            int j = q * 32 + lane;
            v[q] = (2.f * (dt[j] - cr[j]) - qq[j]) * (1.f / 512.f);
        }
        v4 = (lane == 0) ? (2.f * (dt[128] - cr[128]) - qq[128]) * (1.f / 512.f) : -INFINITY;
        float m = fmaxf(fmaxf(fmaxf(v[0], v[1]), fmaxf(v[2], v[3])), v4);
        m = wmax(m);
        float e0 = __expf(v[0] - m), e1 = __expf(v[1] - m);
        float e2 = __expf(v[2] - m), e3 = __expf(v[3] - m);
        float e4 = (lane == 0) ? __expf(v4 - m) : 0.f;
        float s = wsum(e0 + e1 + e2 + e3 + e4);
        float inv = 1.f / s;
        xp2_s[w * 132 + lane]      = e0 * inv;
        xp2_s[w * 132 + 32 + lane] = e1 * inv;
        xp2_s[w * 132 + 64 + lane] = e2 * inv;
        xp2_s[w * 132 + 96 + lane] = e3 * inv;
        if (lane == 0) xp2_s[w * 132 + 128] = e4 * inv;
    }
    __syncthreads();

    for (int i = t; i < 1024; i += 256) {
        int bi = i >> 7, e = i & 127;
        float acc = 0.f;
        const float* xp = xp2_s + bi * 132;
#pragma unroll 4
        for (int j = 0; j < 129; ++j) acc += xp[j] * wrec2_s[j * 129 + e];
        lat2_s[i] = acc;
    }
    __syncthreads();

    for (int i = t; i < 1032; i += 256) {
        unsigned bi = div129((unsigned)i);
        unsigned tt = (unsigned)i - bi * 129u;
        float acc = 0.f;
        const float* lt = lat2_s + bi * 128;
#pragma unroll 4
        for (int e = 0; e < 128; ++e) acc += lt[e] * wrec2_s[tt * 129 + e];
        lg4_s[bi * 132 + tt] = (2.f * acc - d_wrec2norm[tt]) * (1.f / 128.f);
    }
    __syncthreads();

    {
        float v[4];
#pragma unroll
        for (int q = 0; q < 4; ++q) v[q] = lg4_s[w * 132 + q * 32 + lane];
        float v4 = (lane == 0) ? lg4_s[w * 132 + 128] : -INFINITY;
        float m = fmaxf(fmaxf(fmaxf(v[0], v[1]), fmaxf(v[2], v[3])), v4);
        m = wmax(m);
        float e0 = __expf(v[0] - m), e1 = __expf(v[1] - m);
        float e2 = __expf(v[2] - m), e3 = __expf(v[3] - m);
        float e4 = (lane == 0) ? __expf(v4 - m) : 0.f;
        float s = wsum(e0 + e1 + e2 + e3 + e4);
        float inv = 1.f / s;
        d_xp2d[b * J_ + lane]      = e0 * inv;
        d_xp2d[b * J_ + 32 + lane] = e1 * inv;
        d_xp2d[b * J_ + 64 + lane] = e2 * inv;
        d_xp2d[b * J_ + 96 + lane] = e3 * inv;
        if (lane == 0) d_xp2d[b * J_ + 128] = e4 * inv;
    }
}

// ---------------- build P (f16) ----------------
__global__ void k_buildP() {
    __shared__ float xp_s[128];
    __shared__ float xp2_s[132];
    int b = blockIdx.x, t = threadIdx.x;
    if (t < 128) xp_s[t] = d_xpd[b * 128 + t];
    if (t < 129) xp2_s[t] = d_xp2d[b * J_ + t];
    __syncthreads();
    __half2* dst = (__half2*)(d_Ph + (size_t)b * KE2_);
    for (int i2 = t; i2 < KE_ / 2; i2 += 256) {
        int kj = i2 * 2;
        float v0, v1;
        if (kj < KJ_) {
            unsigned k = div129((unsigned)kj);
            unsigned j = (unsigned)kj - k * 129u;
            float xk = xp_s[k];
            v0 = xk * xp2_s[j];
            v1 = (j < 128) ? xk * xp2_s[j + 1] : xp_s[k + 1] * xp2_s[0];
        } else {
            v0 = xp_s[kj - KJ_];
            v1 = xp_s[kj - KJ_ + 1];
        }
        dst[i2] = __floats2half2_rn(v0, v1);
    }
}

// ---------------- f16 mma.sync GEMM: grid (4 g, 8 b, 8 ks), 2 CTAs/SM ----------------
__global__ __launch_bounds__(256, 2)
void k_tgemm() {
    extern __shared__ char smem[];
    uint32_t sb = s2u(smem);
    int tid = threadIdx.x;
    int lane = tid & 31, wid = tid >> 5;
    int wm = wid >> 2, wn = wid & 3;
    int row_l = lane >> 2, kq = lane & 3;
    unsigned axorm = (unsigned)row_l << 4;

    int g0 = blockIdx.x * 128, b0 = blockIdx.y * 128, ks = blockIdx.z;
    int cbase = ks * NCH_;
    const char* pbase = (const char*)(d_Ph + (size_t)b0 * KE2_);
    const char* wbase = (const char*)(d_w2h + (size_t)g0 * KE2_);

    auto fill = [&](int cl, int s) {
        int c = cbase + cl;
        uint32_t asm_ = sb + s * STAGE_B;
        uint32_t bsm = asm_ + 16384;
        const char* psrc = pbase + (size_t)c * 128;
        const char* wsrc = wbase + (size_t)c * 128;
#pragma unroll
        for (int p = 0; p < 4; ++p) {
            int i = tid + p * 256;
            int row = i >> 3;
            int cb = (i & 7) << 4;
            uint32_t sw = SWZ(row * 128 + cb);
            cp16(asm_ + sw, psrc + (size_t)row * (KE2_ * 2) + cb);
            cp16(bsm + sw, wsrc + (size_t)row * (KE2_ * 2) + cb);
        }
    };

    float acc[4][4][4];
#pragma unroll
    for (int mt = 0; mt < 4; ++mt)
#pragma unroll
        for (int nt = 0; nt < 4; ++nt)
#pragma unroll
            for (int q = 0; q < 4; ++q) acc[mt][nt][q] = 0.f;

#pragma unroll
    for (int cl = 0; cl < GSTAGES - 1; ++cl) {
        fill(cl, cl);
        asm volatile("cp.async.commit_group;" ::: "memory");
    }

    for (int it = 0; it < NCH_; ++it) {
        asm volatile("cp.async.wait_group %0;" :: "n"(GSTAGES - 2) : "memory");
        __syncthreads();

        int cf = it + GSTAGES - 1;
        if (cf < NCH_) fill(cf, cf % GSTAGES);
        asm volatile("cp.async.commit_group;" ::: "memory");

        const char* As = smem + (it % GSTAGES) * STAGE_B;
        const char* Bs = As + 16384;

#pragma unroll
        for (int kst = 0; kst < 4; ++kst) {
            uint32_t af[4][4];
#pragma unroll
            for (int mt = 0; mt < 4; ++mt) {
                unsigned m = wm * 64 + mt * 16 + row_l;
                unsigned base = m * 128 + kst * 32 + kq * 4;
                af[mt][0] = *(const uint32_t*)(As + (base ^ axorm));
                af[mt][1] = *(const uint32_t*)(As + ((base + 8 * 128) ^ axorm));
                af[mt][2] = *(const uint32_t*)(As + ((base + 16) ^ axorm));
                af[mt][3] = *(const uint32_t*)(As + ((base + 8 * 128 + 16) ^ axorm));
            }
            uint32_t bf[4][2];
#pragma unroll
            for (int nt = 0; nt < 4; ++nt) {
                unsigned n = wn * 32 + nt * 8 + row_l;
                unsigned base = n * 128 + kst * 32 + kq * 4;
                bf[nt][0] = *(const uint32_t*)(Bs + (base ^ axorm));
                bf[nt][1] = *(const uint32_t*)(Bs + ((base + 16) ^ axorm));
            }
#pragma unroll
            for (int mt = 0; mt < 4; ++mt)
#pragma unroll
                for (int nt = 0; nt < 4; ++nt)
                    mma_f16(acc[mt][nt], af[mt], bf[nt]);
        }
    }

#pragma unroll
    for (int mt = 0; mt < 4; ++mt) {
#pragma unroll
        for (int nt = 0; nt < 4; ++nt) {
            int grow = b0 + wm * 64 + mt * 16 + row_l;
            int gcol = g0 + wn * 32 + nt * 8 + kq * 2;
            *(float2*)&d_c2[ks][grow][gcol]     = make_float2(acc[mt][nt][0], acc[mt][nt][1]);
            *(float2*)&d_c2[ks][grow + 8][gcol] = make_float2(acc[mt][nt][2], acc[mt][nt][3]);
        }
    }
}

// ---------------- final loss ----------------
__global__ void k_loss(const float* __restrict__ images, float* __restrict__ out) {
    int b = blockIdx.x, t = threadIdx.x;
    float s = 0.f;
    for (int g = t; g < 512; g += 128) {
        float v = -images[b * 512 + g];
#pragma unroll
        for (int h = 0; h < NSPLIT_; ++h) v += d_c2[h][b][g];
        s += v * v;
    }
    __shared__ float red[128];
    red[t] = s; __syncthreads();
    for (int q = 64; q; q >>= 1) { if (t < q) red[t] += red[t + q]; __syncthreads(); }
    if (t == 0) out[b] = red[0] * (1.f / 512.f);
}

// ---------------- launch ----------------
extern "C" void kernel_launch(void* const* d_in, const int* in_sizes, int n_in,
                              void* d_out, int out_size) {
    const float* images = (const float*)d_in[0];
    const float* wimg   = (const float*)d_in[1];
    const float* wrec   = (const float*)d_in[2];
    const float* wrec2  = (const float*)d_in[3];
    const float* wimg2  = (const float*)d_in[4];
    float* out = (float*)d_out;

    cudaFuncSetAttribute(k_latlog2, cudaFuncAttributeMaxDynamicSharedMemorySize, SMEM_L2);
    cudaFuncSetAttribute(k_latlog4, cudaFuncAttributeMaxDynamicSharedMemorySize, SMEM_L4);
    cudaFuncSetAttribute(k_tgemm,   cudaFuncAttributeMaxDynamicSharedMemorySize, SMEM_G);

    k_prep1<<<dim3(65, 8), 256>>>(wimg, wimg2);
    k_qred<<<66, 256>>>(wrec, wrec2);
    k_log1t<<<dim3(8, NLS_), 256>>>(images, wimg);
    k_latlog2<<<128, 256, SMEM_L2>>>(wrec);
    k_dot2<<<B_, 256>>>(images);
    k_latlog4<<<128, 256, SMEM_L4>>>(wrec2);
    k_buildP<<<B_, 256>>>();
    k_tgemm<<<dim3(4, 8, NSPLIT_), 256, SMEM_G>>>();
    k_loss<<<B_, 128>>>(images, out);
}

// round 10
// speedup vs baseline: 14.6713x; 1.0941x over previous
#include <cuda_runtime.h>
#include <cuda_fp16.h>
#include <cstdint>

#define B_     1024
#define G_     512
#define K_     128
#define J_     129
#define KJ_    16512
#define KE_    16640
#define KB132_ 16896        // 128 * 132 (k-blocks padded to 132)
#define KEP_   17024        // payload end: KB132_ + 128 (wimg ext)
#define KE3_   17408        // padded to 272 chunks of 64
#define NSPLIT_ 8
#define NCH_   34           // 272 / 8
#define GSTAGES 3
#define STAGE_B 32768
#define SMEM_G (GSTAGES * STAGE_B)
#define NLS_   16

// ---------------- device scratch ----------------
__device__ float d_wrecnorm[K_];
__device__ float d_wrec2norm[J_];
__device__ float d_wnorm1[K_];
__device__ float d_q[KJ_];
__device__ float d_corr[KJ_];
__device__ float d_qp[8][KJ_];
__device__ float d_cp[8][KJ_];
__device__ float d_wnp[8][K_];
__device__ float d_lg1p[NLS_][B_][K_];
__device__ float d_xpd[B_ * K_];
__device__ int   d_idx[B_];
__device__ float d_xp2d[B_ * J_];
__device__ float d_dot2[B_ * J_];
__device__ __half d_Ph[(size_t)B_ * KE3_];
__device__ __half d_w2h[(size_t)G_ * KE3_];   // pads never written -> zero-init
__device__ float d_c2[NSPLIT_][B_][G_];

// ---------------- helpers ----------------
__device__ __forceinline__ uint32_t s2u(const void* p) {
    uint32_t r;
    asm("{ .reg .u64 t; cvta.to.shared.u64 t, %1; cvt.u32.u64 %0, t; }" : "=r"(r) : "l"(p));
    return r;
}
__device__ __forceinline__ void cp16(uint32_t dst, const void* src) {
    asm volatile("cp.async.cg.shared.global [%0], [%1], 16;" :: "r"(dst), "l"(src) : "memory");
}
#define SWZ(o) ((o) ^ ((((unsigned)(o)) >> 3) & 0x70u))

__device__ __forceinline__ void mma_f16(float* c, const uint32_t* a, const uint32_t* b) {
    asm volatile(
        "mma.sync.aligned.m16n8k16.row.col.f32.f16.f16.f32 "
        "{%0,%1,%2,%3}, {%4,%5,%6,%7}, {%8,%9}, {%0,%1,%2,%3};"
        : "+f"(c[0]), "+f"(c[1]), "+f"(c[2]), "+f"(c[3])
        : "r"(a[0]), "r"(a[1]), "r"(a[2]), "r"(a[3]), "r"(b[0]), "r"(b[1]));
}
__device__ __forceinline__ void mma_tf32(float* c, const uint32_t* a, const uint32_t* b) {
    asm volatile(
        "mma.sync.aligned.m16n8k8.row.col.f32.tf32.tf32.f32 "
        "{%0,%1,%2,%3}, {%4,%5,%6,%7}, {%8,%9}, {%0,%1,%2,%3};"
        : "+f"(c[0]), "+f"(c[1]), "+f"(c[2]), "+f"(c[3])
        : "r"(a[0]), "r"(a[1]), "r"(a[2]), "r"(a[3]), "r"(b[0]), "r"(b[1]));
}
__device__ __forceinline__ unsigned div129(unsigned kj) { return (kj * 32515u) >> 22; }
__device__ __forceinline__ unsigned div132(unsigned kj) { return (kj * 31776u) >> 22; } // exact for kj < 16896
__device__ __forceinline__ float wmax(float v) {
#pragma unroll
    for (int o = 16; o; o >>= 1) v = fmaxf(v, __shfl_xor_sync(~0u, v, o));
    return v;
}
__device__ __forceinline__ float wsum(float v) {
#pragma unroll
    for (int o = 16; o; o >>= 1) v += __shfl_xor_sync(~0u, v, o);
    return v;
}

// ---------------- wimg2 pass ----------------
__global__ void k_prep1(const float* __restrict__ wimg,
                        const float* __restrict__ wimg2) {
    int t = blockIdx.x * 256 + threadIdx.x;
    int gh = blockIdx.y;
    int gbeg = gh * 64;
    if (t < KJ_) {
        unsigned k = div129((unsigned)t);
        unsigned j = (unsigned)t - k * 129u;
        size_t woff = k * 132u + j;
        float q = 0.f, c = 0.f;
        for (int gg = 0; gg < 64; ++gg) {
            int g = gbeg + gg;
            float v = wimg2[(size_t)g * KJ_ + t];
            float wi = wimg[g * K_ + k];
            q += v * v;
            c += wi * v;
            d_w2h[(size_t)g * KE3_ + woff] = __float2half(v);
        }
        d_qp[gh][t] = q;
        d_cp[gh][t] = c;
    } else if (t < KE_) {
        int kk = t - KJ_;
        size_t woff = KB132_ + kk;
        float s = 0.f;
        for (int gg = 0; gg < 64; ++gg) {
            int g = gbeg + gg;
            float v = wimg[g * K_ + kk];
            s += v * v;
            d_w2h[(size_t)g * KE3_ + woff] = __float2half(v);
        }
        d_wnp[gh][kk] = s;
    }
}

// grid 66: blocks 0..64 reduce partials, block 65 computes wrec/wrec2 norms
__global__ void k_qred(const float* __restrict__ wrec,
                       const float* __restrict__ wrec2) {
    if (blockIdx.x == 65) {
        int t = threadIdx.x;
        if (t < K_) {
            float s = 0.f; const float* r = wrec + t * 128;
            for (int e = 0; e < 128; ++e) s += r[e] * r[e];
            d_wrecnorm[t] = s;
        }
        if (t < J_) {
            float s = 0.f; const float* r = wrec2 + t * 128;
            for (int e = 0; e < 128; ++e) s += r[e] * r[e];
            d_wrec2norm[t] = s;
        }
        return;
    }
    int t = blockIdx.x * 256 + threadIdx.x;
    if (t < KJ_) {
        float q = 0.f, c = 0.f;
#pragma unroll
        for (int h = 0; h < 8; ++h) { q += d_qp[h][t]; c += d_cp[h][t]; }
        d_q[t] = q;
        d_corr[t] = c;
    } else if (t < KE_) {
        int kk = t - KJ_;
        float s = 0.f;
#pragma unroll
        for (int h = 0; h < 8; ++h) s += d_wnp[h][kk];
        d_wnorm1[kk] = s;
    }
}

// ---------------- logits1 via tf32 mma: grid (8 b-tiles, 16 k-splits) ----------------
__global__ __launch_bounds__(256) void k_log1t(const float* __restrict__ images,
                                               const float* __restrict__ wimg) {
    __shared__ float As[128 * 36];
    __shared__ float Bs[32 * 132];

    int tid = threadIdx.x, lane = tid & 31, wid = tid >> 5;
    int wm = wid >> 2, wn = wid & 3;
    int row_l = lane >> 2, kq = lane & 3;
    int b0 = blockIdx.x * 128, ks = blockIdx.y;
    int g0 = ks * 32;
    uint32_t asb = s2u(As), bsb = s2u(Bs);

    float acc[4][4][4];
#pragma unroll
    for (int mt = 0; mt < 4; ++mt)
#pragma unroll
        for (int nt = 0; nt < 4; ++nt)
#pragma unroll
            for (int q = 0; q < 4; ++q) acc[mt][nt][q] = 0.f;

#pragma unroll
    for (int p = 0; p < 4; ++p) {
        int i = tid + p * 256;
        int row = i >> 3, c4 = (i & 7) << 2;
        cp16(asb + (row * 36 + c4) * 4, images + (size_t)(b0 + row) * 512 + g0 + c4);
    }
#pragma unroll
    for (int p = 0; p < 4; ++p) {
        int i = tid + p * 256;
        int row = i >> 5, c4 = (i & 31) << 2;
        cp16(bsb + (row * 132 + c4) * 4, wimg + (size_t)(g0 + row) * 128 + c4);
    }
    asm volatile("cp.async.commit_group;" ::: "memory");
    asm volatile("cp.async.wait_group 0;" ::: "memory");
    __syncthreads();

#pragma unroll
    for (int kst = 0; kst < 4; ++kst) {
        uint32_t af[4][4];
#pragma unroll
        for (int mt = 0; mt < 4; ++mt) {
            int m = wm * 64 + mt * 16 + row_l;
            const float* ap = As + m * 36 + kst * 8 + kq;
            af[mt][0] = __float_as_uint(ap[0]);
            af[mt][1] = __float_as_uint(ap[8 * 36]);
            af[mt][2] = __float_as_uint(ap[4]);
            af[mt][3] = __float_as_uint(ap[8 * 36 + 4]);
        }
        uint32_t bf[4][2];
#pragma unroll
        for (int nt = 0; nt < 4; ++nt) {
            int n = wn * 32 + nt * 8 + row_l;
            const float* bp = Bs + (kst * 8 + kq) * 132 + n;
            bf[nt][0] = __float_as_uint(bp[0]);
            bf[nt][1] = __float_as_uint(bp[4 * 132]);
        }
#pragma unroll
        for (int mt = 0; mt < 4; ++mt)
#pragma unroll
            for (int nt = 0; nt < 4; ++nt)
                mma_tf32(acc[mt][nt], af[mt], bf[nt]);
    }

#pragma unroll
    for (int mt = 0; mt < 4; ++mt)
#pragma unroll
        for (int nt = 0; nt < 4; ++nt) {
            int row = b0 + wm * 64 + mt * 16 + row_l;
            int col = wn * 32 + nt * 8 + kq * 2;
            *(float2*)&d_lg1p[ks][row][col]     = make_float2(acc[mt][nt][0], acc[mt][nt][1]);
            *(float2*)&d_lg1p[ks][row + 8][col] = make_float2(acc[mt][nt][2], acc[mt][nt][3]);
        }
}

// ---------------- softmax1 -> lat -> logits2 -> softmax2+argmax (float4, stride 132) ----------------
#define SMEM_L2 ((16896 + 1024 + 1024) * 4)
__global__ void k_latlog2(const float* __restrict__ wrec) {
    extern __shared__ float sm[];
    float* wrec_s = sm;              // [128][132]
    float* xp1_s  = wrec_s + 16896;  // [8][128]
    float* lat_s  = xp1_s + 1024;    // [8][128]

    int t = threadIdx.x, lane = t & 31, w = t >> 5;
    int b = blockIdx.x * 8 + w;
    uint32_t wsb = s2u(wrec_s);

    // async fill wrec (128 rows x 8 cp16, stride 132)
#pragma unroll
    for (int p = 0; p < 4; ++p) {
        int i = t + p * 256;
        int row = i >> 3, c4 = (i & 7) << 2;
        cp16(wsb + (row * 132 + c4) * 4, wrec + row * 128 + c4);
    }
    asm volatile("cp.async.commit_group;" ::: "memory");

    // softmax1 from global partials (overlaps the fill)
    {
        float v[4];
#pragma unroll
        for (int q = 0; q < 4; ++q) {
            int k = q * 32 + lane;
            float d = 0.f;
#pragma unroll
            for (int h = 0; h < NLS_; ++h) d += d_lg1p[h][b][k];
            v[q] = (2.f * d - d_wnorm1[k]) * (1.f / 512.f);
        }
        float m = fmaxf(fmaxf(v[0], v[1]), fmaxf(v[2], v[3]));
        m = wmax(m);
        float e0 = __expf(v[0] - m), e1 = __expf(v[1] - m);
        float e2 = __expf(v[2] - m), e3 = __expf(v[3] - m);
        float s = wsum(e0 + e1 + e2 + e3);
        float inv = 1.f / s;
        xp1_s[w * 128 + lane]      = e0 * inv;
        xp1_s[w * 128 + 32 + lane] = e1 * inv;
        xp1_s[w * 128 + 64 + lane] = e2 * inv;
        xp1_s[w * 128 + 96 + lane] = e3 * inv;
    }
    asm volatile("cp.async.wait_group 0;" ::: "memory");
    __syncthreads();

    const float4* w4 = (const float4*)wrec_s;        // row k at k*33
    // GEMV1: lat[w][4*lane..+3] = sum_k xp1[w][k] * wrec[k][...]
    {
        const float4* xp4 = (const float4*)(xp1_s + w * 128);
        float4 acc = make_float4(0.f, 0.f, 0.f, 0.f);
#pragma unroll 8
        for (int k4 = 0; k4 < 32; ++k4) {
            float4 xv = xp4[k4];
            float4 w0 = w4[(4 * k4 + 0) * 33 + lane];
            float4 w1 = w4[(4 * k4 + 1) * 33 + lane];
            float4 w2 = w4[(4 * k4 + 2) * 33 + lane];
            float4 w3 = w4[(4 * k4 + 3) * 33 + lane];
            acc.x += xv.x * w0.x + xv.y * w1.x + xv.z * w2.x + xv.w * w3.x;
            acc.y += xv.x * w0.y + xv.y * w1.y + xv.z * w2.y + xv.w * w3.y;
            acc.z += xv.x * w0.z + xv.y * w1.z + xv.z * w2.z + xv.w * w3.z;
            acc.w += xv.x * w0.w + xv.y * w1.w + xv.z * w2.w + xv.w * w3.w;
        }
        *(float4*)(lat_s + w * 128 + 4 * lane) = acc;
    }
    __syncthreads();

    // GEMV2 (in-register -> softmax): v[q] = lg2[w][lane+32q]
    {
        const float4* l4 = (const float4*)(lat_s + w * 128);
        float v[4] = {0.f, 0.f, 0.f, 0.f};
#pragma unroll 4
        for (int e4 = 0; e4 < 32; ++e4) {
            float4 lv = l4[e4];
#pragma unroll
            for (int q = 0; q < 4; ++q) {
                float4 wv = w4[(lane + 32 * q) * 33 + e4];
                v[q] += lv.x * wv.x + lv.y * wv.y + lv.z * wv.z + lv.w * wv.w;
            }
        }
#pragma unroll
        for (int q = 0; q < 4; ++q) {
            int tt = lane + 32 * q;
            v[q] = (2.f * v[q] - d_wrecnorm[tt]) * (1.f / 128.f);
        }
        float bv = v[0]; int bk = lane;
#pragma unroll
        for (int q = 1; q < 4; ++q)
            if (v[q] > bv) { bv = v[q]; bk = q * 32 + lane; }
#pragma unroll
        for (int o = 16; o; o >>= 1) {
            float ov = __shfl_xor_sync(~0u, bv, o);
            int   ok = __shfl_xor_sync(~0u, bk, o);
            if (ov > bv || (ov == bv && ok < bk)) { bv = ov; bk = ok; }
        }
        if (lane == 0) d_idx[b] = bk;
        float m = bv;
        float e0 = __expf(v[0] - m), e1 = __expf(v[1] - m);
        float e2 = __expf(v[2] - m), e3 = __expf(v[3] - m);
        float s = wsum(e0 + e1 + e2 + e3);
        float inv = 1.f / s;
        d_xpd[b * 128 + lane]      = e0 * inv;
        d_xpd[b * 128 + 32 + lane] = e1 * inv;
        d_xpd[b * 128 + 64 + lane] = e2 * inv;
        d_xpd[b * 128 + 96 + lane] = e3 * inv;
    }
}

// ---------------- dot2: per-b, g-parallel, half2 (132-aligned columns) ----------------
__global__ void k_dot2(const float* __restrict__ images) {
    __shared__ float img_s[512];
    __shared__ float part[8][136];
    int b = blockIdx.x, t = threadIdx.x, lane = t & 31, w = t >> 5;
    for (int i = t; i < 512; i += 256) img_s[i] = images[b * 512 + i];
    __syncthreads();
    int idx = d_idx[b];
    const __half* colb = d_w2h + (size_t)idx * 132;
    float2 a0 = make_float2(0.f, 0.f), a1 = make_float2(0.f, 0.f);
    float a128 = 0.f;
    for (int g = w; g < 512; g += 8) {
        float iv = img_s[g];
        const __half2* rp2 = (const __half2*)(colb + (size_t)g * KE3_);
        float2 f0 = __half22float2(rp2[lane]);
        float2 f1 = __half22float2(rp2[lane + 32]);
        a0.x += iv * f0.x; a0.y += iv * f0.y;
        a1.x += iv * f1.x; a1.y += iv * f1.y;
        if (lane == 0) a128 += iv * __half2float(((const __half*)rp2)[128]);
    }
    part[w][2 * lane]     = a0.x; part[w][2 * lane + 1]  = a0.y;
    part[w][64 + 2 * lane] = a1.x; part[w][65 + 2 * lane] = a1.y;
    if (lane == 0) part[w][128] = a128;
    __syncthreads();
    if (t < 129) {
        float s = 0.f;
#pragma unroll
        for (int ww = 0; ww < 8; ++ww) s += part[ww][t];
        d_dot2[b * J_ + t] = s;
    }
}

// ---------------- softmax3 -> lat2 -> logits4 -> softmax4 (float4, stride 132) ----------------
#define SMEM_L4 ((17028 + 1056 + 1024) * 4)
__global__ void k_latlog4(const float* __restrict__ wrec2) {
    extern __shared__ float sm[];
    float* wrec2_s = sm;               // [129][132]
    float* xp2_s   = wrec2_s + 17028;  // [8][132]
    float* lat2_s  = xp2_s + 1056;     // [8][128]

    int t = threadIdx.x, lane = t & 31, w = t >> 5;
    int b = blockIdx.x * 8 + w;
    int idx = d_idx[b];
    uint32_t wsb = s2u(wrec2_s);

    // async fill wrec2 (129 rows x 8 cp16)
#pragma unroll
    for (int p = 0; p < 5; ++p) {
        int i = t + p * 256;
        if (i < 1032) {
            int row = i >> 3, c4 = (i & 7) << 2;
            cp16(wsb + (row * 132 + c4) * 4, wrec2 + row * 128 + c4);
        }
    }
    asm volatile("cp.async.commit_group;" ::: "memory");

    // softmax3 from global (overlaps fill)
    {
        const float* dt = d_dot2 + b * J_;
        const float* cr = d_corr + idx * J_;
        const float* qq = d_q + idx * J_;
        float v[4], v4;
#pragma unroll
        for (int q = 0; q < 4; ++q) {
            int j = q * 32 + lane;
            v[q] = (2.f * (dt[j] - cr[j]) - qq[j]) * (1.f / 512.f);
        }
        v4 = (lane == 0) ? (2.f * (dt[128] - cr[128]) - qq[128]) * (1.f / 512.f) : -INFINITY;
        float m = fmaxf(fmaxf(fmaxf(v[0], v[1]), fmaxf(v[2], v[3])), v4);
        m = wmax(m);
        float e0 = __expf(v[0] - m), e1 = __expf(v[1] - m);
        float e2 = __expf(v[2] - m), e3 = __expf(v[3] - m);
        float e4 = (lane == 0) ? __expf(v4 - m) : 0.f;
        float s = wsum(e0 + e1 + e2 + e3 + e4);
        float inv = 1.f / s;
        xp2_s[w * 132 + lane]      = e0 * inv;
        xp2_s[w * 132 + 32 + lane] = e1 * inv;
        xp2_s[w * 132 + 64 + lane] = e2 * inv;
        xp2_s[w * 132 + 96 + lane] = e3 * inv;
        if (lane == 0) xp2_s[w * 132 + 128] = e4 * inv;
    }
    asm volatile("cp.async.wait_group 0;" ::: "memory");
    __syncthreads();

    const float4* w4 = (const float4*)wrec2_s;   // row j at j*33
    // GEMV1: lat2[w][4*lane..+3] = sum_{j<129} xp2[w][j] * wrec2[j][...]
    {
        const float4* xp4 = (const float4*)(xp2_s + w * 132);
        float4 acc = make_float4(0.f, 0.f, 0.f, 0.f);
#pragma unroll 8
        for (int j4 = 0; j4 < 32; ++j4) {
            float4 xv = xp4[j4];
            float4 w0 = w4[(4 * j4 + 0) * 33 + lane];
            float4 w1 = w4[(4 * j4 + 1) * 33 + lane];
            float4 w2 = w4[(4 * j4 + 2) * 33 + lane];
            float4 w3 = w4[(4 * j4 + 3) * 33 + lane];
            acc.x += xv.x * w0.x + xv.y * w1.x + xv.z * w2.x + xv.w * w3.x;
            acc.y += xv.x * w0.y + xv.y * w1.y + xv.z * w2.y + xv.w * w3.y;
            acc.z += xv.x * w0.z + xv.y * w1.z + xv.z * w2.z + xv.w * w3.z;
            acc.w += xv.x * w0.w + xv.y * w1.w + xv.z * w2.w + xv.w * w3.w;
        }
        float xs = xp2_s[w * 132 + 128];
        float4 wl = w4[128 * 33 + lane];
        acc.x += xs * wl.x; acc.y += xs * wl.y; acc.z += xs * wl.z; acc.w += xs * wl.w;
        *(float4*)(lat2_s + w * 128 + 4 * lane) = acc;
    }
    __syncthreads();

    // GEMV2 (in-register -> softmax over 129)
    {
        const float4* l4 = (const float4*)(lat2_s + w * 128);
        float v[4] = {0.f, 0.f, 0.f, 0.f};
#pragma unroll 4
        for (int e4 = 0; e4 < 32; ++e4) {
            float4 lv = l4[e4];
#pragma unroll
            for (int q = 0; q < 4; ++q) {
                float4 wv = w4[(lane + 32 * q) * 33 + e4];
                v[q] += lv.x * wv.x + lv.y * wv.y + lv.z * wv.z + lv.w * wv.w;
            }
        }
        float v4 = -INFINITY;
        if (lane == 0) {
            float a = 0.f;
            for (int e4 = 0; e4 < 32; ++e4) {
                float4 lv = l4[e4];
                float4 wv = w4[128 * 33 + e4];
                a += lv.x * wv.x + lv.y * wv.y + lv.z * wv.z + lv.w * wv.w;
            }
            v4 = (2.f * a - d_wrec2norm[128]) * (1.f / 128.f);
        }
#pragma unroll
        for (int q = 0; q < 4; ++q) {
            int tt = lane + 32 * q;
            v[q] = (2.f * v[q] - d_wrec2norm[tt]) * (1.f / 128.f);
        }
        float m = fmaxf(fmaxf(fmaxf(v[0], v[1]), fmaxf(v[2], v[3])), v4);
        m = wmax(m);
        float e0 = __expf(v[0] - m), e1 = __expf(v[1] - m);
        float e2 = __expf(v[2] - m), e3 = __expf(v[3] - m);
        float e4 = (lane == 0) ? __expf(v4 - m) : 0.f;
        float s = wsum(e0 + e1 + e2 + e3 + e4);
        float inv = 1.f / s;
        d_xp2d[b * J_ + lane]      = e0 * inv;
        d_xp2d[b * J_ + 32 + lane] = e1 * inv;
        d_xp2d[b * J_ + 64 + lane] = e2 * inv;
        d_xp2d[b * J_ + 96 + lane] = e3 * inv;
        if (lane == 0) d_xp2d[b * J_ + 128] = e4 * inv;
    }
}

// ---------------- build P (f16, 132-block layout) ----------------
__global__ void k_buildP() {
    __shared__ float xp_s[128];
    __shared__ float xp2_s[132];
    int b = blockIdx.x, t = threadIdx.x;
    if (t < 128) xp_s[t] = d_xpd[b * 128 + t];
    if (t < 129) xp2_s[t] = d_xp2d[b * J_ + t];
    __syncthreads();
    auto pv = [&](unsigned kj) -> float {
        if (kj < KB132_) {
            unsigned k = div132(kj);
            unsigned j = kj - k * 132u;
            return (j < 129u) ? xp_s[k] * xp2_s[j] : 0.f;
        }
        if (kj < KEP_) return xp_s[kj - KB132_];
        return 0.f;
    };
    __half2* dst = (__half2*)(d_Ph + (size_t)b * KE3_);
    for (int i2 = t; i2 < KE3_ / 2; i2 += 256) {
        unsigned kj = (unsigned)i2 * 2u;
        dst[i2] = __floats2half2_rn(pv(kj), pv(kj + 1));
    }
}

// ---------------- f16 mma.sync GEMM: grid (4 g, 8 b, 8 ks), 2 CTAs/SM ----------------
__global__ __launch_bounds__(256, 2)
void k_tgemm() {
    extern __shared__ char smem[];
    uint32_t sb = s2u(smem);
    int tid = threadIdx.x;
    int lane = tid & 31, wid = tid >> 5;
    int wm = wid >> 2, wn = wid & 3;
    int row_l = lane >> 2, kq = lane & 3;
    unsigned axorm = (unsigned)row_l << 4;

    int g0 = blockIdx.x * 128, b0 = blockIdx.y * 128, ks = blockIdx.z;
    int cbase = ks * NCH_;
    const char* pbase = (const char*)(d_Ph + (size_t)b0 * KE3_);
    const char* wbase = (const char*)(d_w2h + (size_t)g0 * KE3_);

    auto fill = [&](int cl, int s) {
        int c = cbase + cl;
        uint32_t asm_ = sb + s * STAGE_B;
        uint32_t bsm = asm_ + 16384;
        const char* psrc = pbase + (size_t)c * 128;
        const char* wsrc = wbase + (size_t)c * 128;
#pragma unroll
        for (int p = 0; p < 4; ++p) {
            int i = tid + p * 256;
            int row = i >> 3;
            int cb = (i & 7) << 4;
            uint32_t sw = SWZ(row * 128 + cb);
            cp16(asm_ + sw, psrc + (size_t)row * (KE3_ * 2) + cb);
            cp16(bsm + sw, wsrc + (size_t)row * (KE3_ * 2) + cb);
        }
    };

    float acc[4][4][4];
#pragma unroll
    for (int mt = 0; mt < 4; ++mt)
#pragma unroll
        for (int nt = 0; nt < 4; ++nt)
#pragma unroll
            for (int q = 0; q < 4; ++q) acc[mt][nt][q] = 0.f;

#pragma unroll
    for (int cl = 0; cl < GSTAGES - 1; ++cl) {
        fill(cl, cl);
        asm volatile("cp.async.commit_group;" ::: "memory");
    }

    for (int it = 0; it < NCH_; ++it) {
        asm volatile("cp.async.wait_group %0;" :: "n"(GSTAGES - 2) : "memory");
        __syncthreads();

        int cf = it + GSTAGES - 1;
        if (cf < NCH_) fill(cf, cf % GSTAGES);
        asm volatile("cp.async.commit_group;" ::: "memory");

        const char* As = smem + (it % GSTAGES) * STAGE_B;
        const char* Bs = As + 16384;

#pragma unroll
        for (int kst = 0; kst < 4; ++kst) {
            uint32_t af[4][4];
#pragma unroll
            for (int mt = 0; mt < 4; ++mt) {
                unsigned m = wm * 64 + mt * 16 + row_l;
                unsigned base = m * 128 + kst * 32 + kq * 4;
                af[mt][0] = *(const uint32_t*)(As + (base ^ axorm));
                af[mt][1] = *(const uint32_t*)(As + ((base + 8 * 128) ^ axorm));
                af[mt][2] = *(const uint32_t*)(As + ((base + 16) ^ axorm));
                af[mt][3] = *(const uint32_t*)(As + ((base + 8 * 128 + 16) ^ axorm));
            }
            uint32_t bf[4][2];
#pragma unroll
            for (int nt = 0; nt < 4; ++nt) {
                unsigned n = wn * 32 + nt * 8 + row_l;
                unsigned base = n * 128 + kst * 32 + kq * 4;
                bf[nt][0] = *(const uint32_t*)(Bs + (base ^ axorm));
                bf[nt][1] = *(const uint32_t*)(Bs + ((base + 16) ^ axorm));
            }
#pragma unroll
            for (int mt = 0; mt < 4; ++mt)
#pragma unroll
                for (int nt = 0; nt < 4; ++nt)
                    mma_f16(acc[mt][nt], af[mt], bf[nt]);
        }
    }

#pragma unroll
    for (int mt = 0; mt < 4; ++mt) {
#pragma unroll
        for (int nt = 0; nt < 4; ++nt) {
            int grow = b0 + wm * 64 + mt * 16 + row_l;
            int gcol = g0 + wn * 32 + nt * 8 + kq * 2;
            *(float2*)&d_c2[ks][grow][gcol]     = make_float2(acc[mt][nt][0], acc[mt][nt][1]);
            *(float2*)&d_c2[ks][grow + 8][gcol] = make_float2(acc[mt][nt][2], acc[mt][nt][3]);
        }
    }
}

// ---------------- final loss ----------------
__global__ void k_loss(const float* __restrict__ images, float* __restrict__ out) {
    int b = blockIdx.x, t = threadIdx.x;
    float s = 0.f;
    for (int g = t; g < 512; g += 128) {
        float v = -images[b * 512 + g];
#pragma unroll
        for (int h = 0; h < NSPLIT_; ++h) v += d_c2[h][b][g];
        s += v * v;
    }
    __shared__ float red[128];
    red[t] = s; __syncthreads();
    for (int q = 64; q; q >>= 1) { if (t < q) red[t] += red[t + q]; __syncthreads(); }
    if (t == 0) out[b] = red[0] * (1.f / 512.f);
}

// ---------------- launch ----------------
extern "C" void kernel_launch(void* const* d_in, const int* in_sizes, int n_in,
                              void* d_out, int out_size) {
    const float* images = (const float*)d_in[0];
    const float* wimg   = (const float*)d_in[1];
    const float* wrec   = (const float*)d_in[2];
    const float* wrec2  = (const float*)d_in[3];
    const float* wimg2  = (const float*)d_in[4];
    float* out = (float*)d_out;

    cudaFuncSetAttribute(k_latlog2, cudaFuncAttributeMaxDynamicSharedMemorySize, SMEM_L2);
    cudaFuncSetAttribute(k_latlog4, cudaFuncAttributeMaxDynamicSharedMemorySize, SMEM_L4);
    cudaFuncSetAttribute(k_tgemm,   cudaFuncAttributeMaxDynamicSharedMemorySize, SMEM_G);

    k_prep1<<<dim3(65, 8), 256>>>(wimg, wimg2);
    k_qred<<<66, 256>>>(wrec, wrec2);
    k_log1t<<<dim3(8, NLS_), 256>>>(images, wimg);
    k_latlog2<<<128, 256, SMEM_L2>>>(wrec);
    k_dot2<<<B_, 256>>>(images);
    k_latlog4<<<128, 256, SMEM_L4>>>(wrec2);
    k_buildP<<<B_, 256>>>();
    k_tgemm<<<dim3(4, 8, NSPLIT_), 256, SMEM_G>>>();
    k_loss<<<B_, 128>>>(images, out);
}